// round 5
// baseline (speedup 1.0000x reference)
#include <cuda_runtime.h>
#include <cuda_bf16.h>
#include <math.h>
#include <cstdint>

// ---------------- problem constants ----------------
#define NB     32
#define SEQ    197
#define DMODEL 768
#define NHEAD  12
#define DHEAD  64
#define LAYERS 12
#define MLPD   3072
#define OUTD   1000
#define PPATCH 196
#define IN_DIM 768
#define NS     (NB * SEQ)       // 6304 tokens
#define NP     (NB * PPATCH)    // 6272 patches

// ---------------- device scratch ----------------
__device__ float g_patches[NP * IN_DIM];
__device__ float g_x[NS * DMODEL];
__device__ float g_h[NS * DMODEL];
__device__ float g_q[NS * DMODEL];
__device__ float g_k[NS * DMODEL];
__device__ float g_v[NS * DMODEL];
__device__ float g_mlp[NS * MLPD];

__device__ __forceinline__ float tf32r(float x)
{
    float r;
    asm("cvt.rna.tf32.f32 %0, %1;" : "=f"(r) : "f"(x));
    return r;
}

// ---------------- patchify ----------------
__global__ void __launch_bounds__(256)
patchify_kernel(const float* __restrict__ img)
{
    int idx = blockIdx.x * 256 + threadIdx.x;
    if (idx >= NP * IN_DIM) return;
    int t = idx / IN_DIM;
    int e = idx - t * IN_DIM;
    int n = t / PPATCH;
    int p = t - n * PPATCH;
    int py = p / 14, px = p - py * 14;
    int c  = e >> 8;
    int r  = e & 255;
    int ph = r >> 4, pw = r & 15;
    g_patches[idx] = img[(((size_t)n * 3 + c) * 224 + (py * 16 + ph)) * 224 + px * 16 + pw];
}

// ---------------- assemble ----------------
__global__ void __launch_bounds__(256)
assemble_kernel(const float* __restrict__ tokens, const float* __restrict__ cls,
                const float* __restrict__ pos)
{
    int idx = blockIdx.x * 256 + threadIdx.x;
    if (idx >= NS * DMODEL) return;
    int t = idx / DMODEL;
    int d = idx - t * DMODEL;
    int n = t / SEQ;
    int s = t - n * SEQ;
    float v = (s == 0) ? cls[d] : tokens[((size_t)(n * PPATCH + s - 1)) * DMODEL + d];
    g_x[idx] = v + pos[s * DMODEL + d];
}

// ---------------- pipelined tf32 GEMM: C = A@B + bias (+epilogue) ----------------
// Block 128x128, BK=32, 2-stage cp.async double buffering, dynamic smem.
// As layout [buf][m][k] (stride 36), Bs layout [buf][k][n] (stride 132).
// EPI: 0 = bias, 1 = bias + exact GELU, 2 = bias + residual add
#define TG_SMEM ((2 * 128 * 36 + 2 * 32 * 132) * 4)   // 70656 bytes

template<int EPI>
__global__ void __launch_bounds__(256)
tgemm128(const float* __restrict__ A, const float* __restrict__ B,
         const float* __restrict__ bias, const float* __restrict__ res,
         float* __restrict__ C, int M, int N, int K)
{
    extern __shared__ float smem[];
    float (*As)[128][36]  = reinterpret_cast<float(*)[128][36]>(smem);
    float (*Bs)[32][132]  = reinterpret_cast<float(*)[32][132]>(smem + 2 * 128 * 36);

    const int tid  = threadIdx.x;
    const int wid  = tid >> 5;
    const int lane = tid & 31;
    const int g    = lane >> 2;
    const int tig  = lane & 3;
    const int mw   = wid & 3;
    const int nw   = wid >> 2;
    const int bm   = blockIdx.y * 128;
    const int bn   = blockIdx.x * 128;

    float acc[2][8][4];
    #pragma unroll
    for (int i = 0; i < 2; i++)
        #pragma unroll
        for (int j = 0; j < 8; j++)
            #pragma unroll
            for (int c = 0; c < 4; c++) acc[i][j][c] = 0.f;

    // async tile loader
    auto load_tiles = [&](int kk0, int buf) {
        #pragma unroll
        for (int p = 0; p < 4; p++) {
            int idx = p * 256 + tid;
            int m   = idx >> 3;
            int c4  = (idx & 7) * 4;
            const float* src = A + (size_t)(bm + m) * K + kk0 + c4;
            uint32_t dst = (uint32_t)__cvta_generic_to_shared(&As[buf][m][c4]);
            int sz = (bm + m) < M ? 16 : 0;
            asm volatile("cp.async.cg.shared.global [%0], [%1], 16, %2;"
                         :: "r"(dst), "l"(src), "r"(sz) : "memory");
        }
        #pragma unroll
        for (int p = 0; p < 4; p++) {
            int idx = p * 256 + tid;
            int kr  = idx >> 5;
            int n4  = (idx & 31) * 4;
            const float* src = B + (size_t)(kk0 + kr) * N + bn + n4;
            uint32_t dst = (uint32_t)__cvta_generic_to_shared(&Bs[buf][kr][n4]);
            asm volatile("cp.async.cg.shared.global [%0], [%1], 16;"
                         :: "r"(dst), "l"(src) : "memory");
        }
        asm volatile("cp.async.commit_group;" ::: "memory");
    };

    const int T = K >> 5;
    load_tiles(0, 0);

    for (int kt = 0; kt < T; kt++) {
        const int buf = kt & 1;
        if (kt + 1 < T) {
            load_tiles((kt + 1) << 5, (kt + 1) & 1);
            asm volatile("cp.async.wait_group 1;" ::: "memory");
        } else {
            asm volatile("cp.async.wait_group 0;" ::: "memory");
        }
        __syncthreads();

        #pragma unroll
        for (int ks = 0; ks < 4; ks++) {
            const int kk = ks * 8;
            uint32_t af[2][4];
            #pragma unroll
            for (int mt = 0; mt < 2; mt++) {
                int rb = mw * 32 + mt * 16;
                af[mt][0] = __float_as_uint(tf32r(As[buf][rb + g]    [kk + tig]));
                af[mt][1] = __float_as_uint(tf32r(As[buf][rb + g + 8][kk + tig]));
                af[mt][2] = __float_as_uint(tf32r(As[buf][rb + g]    [kk + tig + 4]));
                af[mt][3] = __float_as_uint(tf32r(As[buf][rb + g + 8][kk + tig + 4]));
            }
            uint32_t bf[8][2];
            #pragma unroll
            for (int nt = 0; nt < 8; nt++) {
                int cb = nw * 64 + nt * 8 + g;
                bf[nt][0] = __float_as_uint(tf32r(Bs[buf][kk + tig]    [cb]));
                bf[nt][1] = __float_as_uint(tf32r(Bs[buf][kk + tig + 4][cb]));
            }
            #pragma unroll
            for (int mt = 0; mt < 2; mt++)
                #pragma unroll
                for (int nt = 0; nt < 8; nt++) {
                    asm volatile(
                        "mma.sync.aligned.m16n8k8.row.col.f32.tf32.tf32.f32 "
                        "{%0,%1,%2,%3},{%4,%5,%6,%7},{%8,%9},{%0,%1,%2,%3};"
                        : "+f"(acc[mt][nt][0]), "+f"(acc[mt][nt][1]),
                          "+f"(acc[mt][nt][2]), "+f"(acc[mt][nt][3])
                        : "r"(af[mt][0]), "r"(af[mt][1]), "r"(af[mt][2]), "r"(af[mt][3]),
                          "r"(bf[nt][0]), "r"(bf[nt][1]));
                }
        }
        __syncthreads();
    }

    // epilogue
    #pragma unroll
    for (int mt = 0; mt < 2; mt++) {
        int r0 = bm + mw * 32 + mt * 16 + g;
        int r1 = r0 + 8;
        #pragma unroll
        for (int nt = 0; nt < 8; nt++) {
            int c0 = bn + nw * 64 + nt * 8 + 2 * tig;
            float b0 = bias[c0], b1 = bias[c0 + 1];
            #pragma unroll
            for (int half = 0; half < 2; half++) {
                int row = half ? r1 : r0;
                if (row >= M) continue;
                float v0 = acc[mt][nt][half * 2 + 0] + b0;
                float v1 = acc[mt][nt][half * 2 + 1] + b1;
                if (EPI == 1) {
                    v0 = 0.5f * v0 * (1.f + erff(v0 * 0.70710678118654752f));
                    v1 = 0.5f * v1 * (1.f + erff(v1 * 0.70710678118654752f));
                }
                if (EPI == 2) {
                    const float2 rr = *(const float2*)(res + (size_t)row * N + c0);
                    v0 += rr.x; v1 += rr.y;
                }
                float2 o; o.x = v0; o.y = v1;
                *(float2*)(C + (size_t)row * N + c0) = o;
            }
        }
    }
}

// ---------------- LayerNorm ----------------
__global__ void __launch_bounds__(256)
ln_kernel(const float* __restrict__ x, const float* __restrict__ g,
          const float* __restrict__ b, float* __restrict__ o)
{
    int row = blockIdx.x;
    int tid = threadIdx.x;
    const float* xr = x + (size_t)row * DMODEL;
    float v0 = xr[tid], v1 = xr[tid + 256], v2 = xr[tid + 512];

    __shared__ float red[10];
    float s = v0 + v1 + v2;
    #pragma unroll
    for (int of = 16; of; of >>= 1) s += __shfl_xor_sync(~0u, s, of);
    if ((tid & 31) == 0) red[tid >> 5] = s;
    __syncthreads();
    if (tid == 0) {
        float t = 0.f;
        #pragma unroll
        for (int i = 0; i < 8; i++) t += red[i];
        red[8] = t * (1.f / 768.f);
    }
    __syncthreads();
    float mu = red[8];
    float d0 = v0 - mu, d1 = v1 - mu, d2 = v2 - mu;
    float q = d0 * d0 + d1 * d1 + d2 * d2;
    #pragma unroll
    for (int of = 16; of; of >>= 1) q += __shfl_xor_sync(~0u, q, of);
    if ((tid & 31) == 0) red[tid >> 5] = q;
    __syncthreads();
    if (tid == 0) {
        float t = 0.f;
        #pragma unroll
        for (int i = 0; i < 8; i++) t += red[i];
        red[9] = rsqrtf(t * (1.f / 768.f) + 1e-5f);
    }
    __syncthreads();
    float inv = red[9];
    float* orow = o + (size_t)row * DMODEL;
    orow[tid]       = d0 * inv * g[tid]       + b[tid];
    orow[tid + 256] = d1 * inv * g[tid + 256] + b[tid + 256];
    orow[tid + 512] = d2 * inv * g[tid + 512] + b[tid + 512];
}

// ---------------- per-head QKV projection ----------------
__global__ void __launch_bounds__(256)
qkv_kernel(const float* __restrict__ h,
           const float* __restrict__ Wq, const float* __restrict__ Wk, const float* __restrict__ Wv,
           const float* __restrict__ bq, const float* __restrict__ bk, const float* __restrict__ bv,
           float* __restrict__ q, float* __restrict__ k, float* __restrict__ v)
{
    int t0 = blockIdx.x * 64;
    int hh = blockIdx.y;
    int z  = blockIdx.z;
    const float* W  = (z == 0) ? Wq : (z == 1) ? Wk : Wv;
    const float* bb = (z == 0) ? bq : (z == 1) ? bk : bv;
    float* out      = (z == 0) ? q  : (z == 1) ? k  : v;
    W  += hh * 64 * 64;
    bb += hh * 64;

    __shared__ float Xs[64][64];
    __shared__ float Ws[64][64];
    int tid = threadIdx.x;
    #pragma unroll
    for (int r = 0; r < 4; r++) {
        int row = (tid >> 4) + r * 16;
        int col = (tid & 15) * 4;
        int tok = t0 + row;
        float4 xv = make_float4(0.f, 0.f, 0.f, 0.f);
        if (tok < NS) xv = *(const float4*)(h + (size_t)tok * DMODEL + hh * 64 + col);
        Xs[col + 0][row] = xv.x; Xs[col + 1][row] = xv.y;
        Xs[col + 2][row] = xv.z; Xs[col + 3][row] = xv.w;
        float4 wv = *(const float4*)(W + row * 64 + col);
        Ws[row][col + 0] = wv.x; Ws[row][col + 1] = wv.y;
        Ws[row][col + 2] = wv.z; Ws[row][col + 3] = wv.w;
    }
    __syncthreads();

    int trr = (tid >> 4) * 4;
    int tcc = (tid & 15) * 4;
    float acc[4][4] = {};
    #pragma unroll
    for (int d = 0; d < 64; d++) {
        float ra[4], rb[4];
        #pragma unroll
        for (int i = 0; i < 4; i++) ra[i] = Xs[d][trr + i];
        #pragma unroll
        for (int j = 0; j < 4; j++) rb[j] = Ws[d][tcc + j];
        #pragma unroll
        for (int i = 0; i < 4; i++)
            #pragma unroll
            for (int j = 0; j < 4; j++)
                acc[i][j] = fmaf(ra[i], rb[j], acc[i][j]);
    }
    #pragma unroll
    for (int i = 0; i < 4; i++) {
        int tok = t0 + trr + i;
        if (tok >= NS) continue;
        #pragma unroll
        for (int j = 0; j < 4; j++)
            out[(size_t)tok * DMODEL + hh * 64 + tcc + j] = acc[i][j] + bb[tcc + j];
    }
}

// ---------------- fused flash attention: O = softmax(QK^T/8) V, x += O ----------------
// Block: 64 queries of one (n,h); streams 4 key tiles of 64. Dynamic smem 64KB.
#define ATTN_SMEM (4 * 64 * 64 * 4)

__global__ void __launch_bounds__(256)
attn_kernel(const float* __restrict__ q, const float* __restrict__ k,
            const float* __restrict__ v, float* __restrict__ x)
{
    extern __shared__ float sm[];
    float (*Qs)[64] = reinterpret_cast<float(*)[64]>(sm);           // [e][q]
    float (*Ks)[64] = reinterpret_cast<float(*)[64]>(sm + 4096);    // [e][k]
    float (*Vs)[64] = reinterpret_cast<float(*)[64]>(sm + 8192);    // [k][e]
    float (*Ps)[64] = reinterpret_cast<float(*)[64]>(sm + 12288);   // [k][q]

    const int q0 = blockIdx.x * 64;
    const int b  = blockIdx.y;
    const int n  = b / NHEAD, hh = b - n * NHEAD;
    const int tid = threadIdx.x;
    const int tr = (tid >> 4) * 4;
    const int tc = (tid & 15) * 4;

    // load Q tile -> Qs[e][q]
    #pragma unroll
    for (int r = 0; r < 4; r++) {
        int row = (tid >> 4) + r * 16;
        int col = (tid & 15) * 4;
        int qt = q0 + row;
        float4 qv = make_float4(0.f, 0.f, 0.f, 0.f);
        if (qt < SEQ) qv = *(const float4*)(q + (size_t)(n * SEQ + qt) * DMODEL + hh * 64 + col);
        Qs[col + 0][row] = qv.x; Qs[col + 1][row] = qv.y;
        Qs[col + 2][row] = qv.z; Qs[col + 3][row] = qv.w;
    }

    float m_run[4], l_run[4], acc[4][4];
    #pragma unroll
    for (int i = 0; i < 4; i++) {
        m_run[i] = -1e30f; l_run[i] = 0.f;
        #pragma unroll
        for (int j = 0; j < 4; j++) acc[i][j] = 0.f;
    }

    for (int kt = 0; kt < 4; kt++) {
        const int k0 = kt * 64;
        __syncthreads();   // prev-iter contraction done before overwriting Ks/Vs/Ps

        // load K tile -> Ks[e][k], V tile -> Vs[k][e]
        #pragma unroll
        for (int r = 0; r < 4; r++) {
            int row = (tid >> 4) + r * 16;
            int col = (tid & 15) * 4;
            int ktok = k0 + row;
            float4 kv = make_float4(0.f, 0.f, 0.f, 0.f);
            float4 vv = make_float4(0.f, 0.f, 0.f, 0.f);
            if (ktok < SEQ) {
                kv = *(const float4*)(k + (size_t)(n * SEQ + ktok) * DMODEL + hh * 64 + col);
                vv = *(const float4*)(v + (size_t)(n * SEQ + ktok) * DMODEL + hh * 64 + col);
            }
            Ks[col + 0][row] = kv.x; Ks[col + 1][row] = kv.y;
            Ks[col + 2][row] = kv.z; Ks[col + 3][row] = kv.w;
            Vs[row][col + 0] = vv.x; Vs[row][col + 1] = vv.y;
            Vs[row][col + 2] = vv.z; Vs[row][col + 3] = vv.w;
        }
        __syncthreads();

        // S = Q K^T
        float s[4][4] = {};
        #pragma unroll
        for (int e = 0; e < 64; e++) {
            float ra[4], rb[4];
            #pragma unroll
            for (int i = 0; i < 4; i++) ra[i] = Qs[e][tr + i];
            #pragma unroll
            for (int j = 0; j < 4; j++) rb[j] = Ks[e][tc + j];
            #pragma unroll
            for (int i = 0; i < 4; i++)
                #pragma unroll
                for (int j = 0; j < 4; j++)
                    s[i][j] = fmaf(ra[i], rb[j], s[i][j]);
        }
        // scale + key mask
        #pragma unroll
        for (int i = 0; i < 4; i++)
            #pragma unroll
            for (int j = 0; j < 4; j++)
                s[i][j] = (k0 + tc + j < SEQ) ? s[i][j] * 0.125f : -1e30f;

        // online softmax stats (row group = 16 lanes sharing tid>>4)
        #pragma unroll
        for (int i = 0; i < 4; i++) {
            float mt_ = fmaxf(fmaxf(s[i][0], s[i][1]), fmaxf(s[i][2], s[i][3]));
            #pragma unroll
            for (int of = 1; of < 16; of <<= 1)
                mt_ = fmaxf(mt_, __shfl_xor_sync(~0u, mt_, of));
            float mnew = fmaxf(m_run[i], mt_);
            float sc = expf(m_run[i] - mnew);
            float rs = 0.f;
            #pragma unroll
            for (int j = 0; j < 4; j++) {
                float p = expf(s[i][j] - mnew);
                s[i][j] = p;
                rs += p;
            }
            #pragma unroll
            for (int of = 1; of < 16; of <<= 1)
                rs += __shfl_xor_sync(~0u, rs, of);
            l_run[i] = l_run[i] * sc + rs;
            #pragma unroll
            for (int j = 0; j < 4; j++) acc[i][j] *= sc;
            m_run[i] = mnew;
        }

        // stage P -> Ps[k][q]
        #pragma unroll
        for (int i = 0; i < 4; i++)
            #pragma unroll
            for (int j = 0; j < 4; j++)
                Ps[tc + j][tr + i] = s[i][j];
        __syncthreads();

        // O += P @ V
        #pragma unroll
        for (int kk = 0; kk < 64; kk++) {
            float ra[4], rb[4];
            #pragma unroll
            for (int i = 0; i < 4; i++) ra[i] = Ps[kk][tr + i];
            #pragma unroll
            for (int j = 0; j < 4; j++) rb[j] = Vs[kk][tc + j];
            #pragma unroll
            for (int i = 0; i < 4; i++)
                #pragma unroll
                for (int j = 0; j < 4; j++)
                    acc[i][j] = fmaf(ra[i], rb[j], acc[i][j]);
        }
    }

    // epilogue: x += O / l
    #pragma unroll
    for (int i = 0; i < 4; i++) {
        int qi = q0 + tr + i;
        if (qi >= SEQ) continue;
        float inv = 1.f / l_run[i];
        #pragma unroll
        for (int j = 0; j < 4; j++) {
            size_t idx = (size_t)(n * SEQ + qi) * DMODEL + hh * 64 + tc + j;
            x[idx] += acc[i][j] * inv;
        }
    }
}

// ---------------- head + softmax ----------------
__global__ void __launch_bounds__(256)
head_kernel(const float* __restrict__ x, const float* __restrict__ Wh,
            const float* __restrict__ bh, float* __restrict__ out)
{
    __shared__ float xs[DMODEL];
    __shared__ float lg[OUTD];
    __shared__ float red[256];
    int n = blockIdx.x, tid = threadIdx.x;
    for (int i = tid; i < DMODEL; i += 256) xs[i] = x[(size_t)n * SEQ * DMODEL + i];
    __syncthreads();
    for (int o = tid; o < OUTD; o += 256) {
        float a = bh[o];
        for (int kk = 0; kk < DMODEL; kk++)
            a = fmaf(xs[kk], Wh[(size_t)kk * OUTD + o], a);
        lg[o] = a;
    }
    __syncthreads();
    float m = -1e30f;
    for (int o = tid; o < OUTD; o += 256) m = fmaxf(m, lg[o]);
    red[tid] = m; __syncthreads();
    for (int s = 128; s; s >>= 1) { if (tid < s) red[tid] = fmaxf(red[tid], red[tid + s]); __syncthreads(); }
    float mx = red[0]; __syncthreads();
    float sm = 0.f;
    for (int o = tid; o < OUTD; o += 256) sm += expf(lg[o] - mx);
    red[tid] = sm; __syncthreads();
    for (int s = 128; s; s >>= 1) { if (tid < s) red[tid] += red[tid + s]; __syncthreads(); }
    float inv = 1.f / red[0];
    __syncthreads();
    for (int o = tid; o < OUTD; o += 256)
        out[(size_t)n * OUTD + o] = expf(lg[o] - mx) * inv;
}

// ---------------- host orchestration ----------------
extern "C" void kernel_launch(void* const* d_in, const int* in_sizes, int n_in,
                              void* d_out, int out_size)
{
    const float* images   = (const float*)d_in[0];
    const float* W_map    = (const float*)d_in[1];
    const float* b_map    = (const float*)d_in[2];
    const float* cls      = (const float*)d_in[3];
    const float* pos      = (const float*)d_in[4];
    const float* ln1_g    = (const float*)d_in[5];
    const float* ln1_b    = (const float*)d_in[6];
    const float* Wq       = (const float*)d_in[7];
    const float* bq       = (const float*)d_in[8];
    const float* Wk       = (const float*)d_in[9];
    const float* bk       = (const float*)d_in[10];
    const float* Wv       = (const float*)d_in[11];
    const float* bv       = (const float*)d_in[12];
    const float* ln2_g    = (const float*)d_in[13];
    const float* ln2_b    = (const float*)d_in[14];
    const float* W1       = (const float*)d_in[15];
    const float* b1       = (const float*)d_in[16];
    const float* W2       = (const float*)d_in[17];
    const float* b2       = (const float*)d_in[18];
    const float* W_head   = (const float*)d_in[19];
    const float* b_head   = (const float*)d_in[20];
    float* out = (float*)d_out;

    float *p_patches, *p_x, *p_h, *p_q, *p_k, *p_v, *p_mlp;
    cudaGetSymbolAddress((void**)&p_patches, g_patches);
    cudaGetSymbolAddress((void**)&p_x, g_x);
    cudaGetSymbolAddress((void**)&p_h, g_h);
    cudaGetSymbolAddress((void**)&p_q, g_q);
    cudaGetSymbolAddress((void**)&p_k, g_k);
    cudaGetSymbolAddress((void**)&p_v, g_v);
    cudaGetSymbolAddress((void**)&p_mlp, g_mlp);

    cudaFuncSetAttribute(tgemm128<0>, cudaFuncAttributeMaxDynamicSharedMemorySize, TG_SMEM);
    cudaFuncSetAttribute(tgemm128<1>, cudaFuncAttributeMaxDynamicSharedMemorySize, TG_SMEM);
    cudaFuncSetAttribute(tgemm128<2>, cudaFuncAttributeMaxDynamicSharedMemorySize, TG_SMEM);
    cudaFuncSetAttribute(attn_kernel, cudaFuncAttributeMaxDynamicSharedMemorySize, ATTN_SMEM);

    // 1) patchify + embed + assemble
    patchify_kernel<<<(NP * IN_DIM) / 256, 256>>>(images);
    {
        dim3 grid(DMODEL / 128, NP / 128);   // 6 x 49
        tgemm128<0><<<grid, 256, TG_SMEM>>>(p_patches, W_map, b_map, nullptr, p_mlp,
                                            NP, DMODEL, IN_DIM);
    }
    assemble_kernel<<<(NS * DMODEL) / 256, 256>>>(p_mlp, cls, pos);

    // 2) transformer blocks
    for (int l = 0; l < LAYERS; l++) {
        ln_kernel<<<NS, 256>>>(p_x, ln1_g + l * DMODEL, ln1_b + l * DMODEL, p_h);

        {
            dim3 grid((NS + 63) / 64, NHEAD, 3);
            qkv_kernel<<<grid, 256>>>(p_h,
                Wq + (size_t)l * NHEAD * DHEAD * DHEAD,
                Wk + (size_t)l * NHEAD * DHEAD * DHEAD,
                Wv + (size_t)l * NHEAD * DHEAD * DHEAD,
                bq + (size_t)l * NHEAD * DHEAD,
                bk + (size_t)l * NHEAD * DHEAD,
                bv + (size_t)l * NHEAD * DHEAD,
                p_q, p_k, p_v);
        }
        {
            dim3 grid((SEQ + 63) / 64, NB * NHEAD);   // 4 x 384
            attn_kernel<<<grid, 256, ATTN_SMEM>>>(p_q, p_k, p_v, p_x);
        }

        ln_kernel<<<NS, 256>>>(p_x, ln2_g + l * DMODEL, ln2_b + l * DMODEL, p_h);
        {
            dim3 grid(MLPD / 128, (NS + 127) / 128);   // 24 x 50
            tgemm128<1><<<grid, 256, TG_SMEM>>>(p_h, W1 + (size_t)l * DMODEL * MLPD,
                                                b1 + (size_t)l * MLPD, nullptr, p_mlp,
                                                NS, MLPD, DMODEL);
        }
        {
            dim3 grid(DMODEL / 128, (NS + 127) / 128); // 6 x 50
            tgemm128<2><<<grid, 256, TG_SMEM>>>(p_mlp, W2 + (size_t)l * MLPD * DMODEL,
                                                b2 + (size_t)l * DMODEL, p_x, p_x,
                                                NS, DMODEL, MLPD);
        }
    }

    // 3) head + softmax
    head_kernel<<<NB, 256>>>(p_x, W_head, b_head, out);
}

// round 6
// speedup vs baseline: 1.6811x; 1.6811x over previous
#include <cuda_runtime.h>
#include <cuda_bf16.h>
#include <math.h>
#include <cstdint>

// ---------------- problem constants ----------------
#define NB     32
#define SEQ    197
#define DMODEL 768
#define NHEAD  12
#define DHEAD  64
#define LAYERS 12
#define MLPD   3072
#define OUTD   1000
#define PPATCH 196
#define IN_DIM 768
#define NS     (NB * SEQ)       // 6304 tokens
#define NP     (NB * PPATCH)    // 6272 patches

// ---------------- device scratch ----------------
__device__ float g_patches[NP * IN_DIM];
__device__ float g_x[NS * DMODEL];
__device__ float g_h[NS * DMODEL];
__device__ float g_q[NS * DMODEL];
__device__ float g_k[NS * DMODEL];
__device__ float g_v[NS * DMODEL];
__device__ float g_mlp[NS * MLPD];
// pre-rounded (tf32 RNA) weight copies
__device__ float g_wmap[IN_DIM * DMODEL];
__device__ float g_w1[LAYERS * DMODEL * MLPD];
__device__ float g_w2[LAYERS * MLPD * DMODEL];

__device__ __forceinline__ float tf32r(float x)
{
    float r;
    asm("cvt.rna.tf32.f32 %0, %1;" : "=f"(r) : "f"(x));
    return r;
}

// ---------------- weight pre-rounding (fp32 -> tf32 bits, RNA) ----------------
__global__ void __launch_bounds__(256)
cvt_kernel(const float* __restrict__ src, float* __restrict__ dst, int n4)
{
    int i = blockIdx.x * 256 + threadIdx.x;
    if (i >= n4) return;
    float4 v = ((const float4*)src)[i];
    v.x = tf32r(v.x); v.y = tf32r(v.y); v.z = tf32r(v.z); v.w = tf32r(v.w);
    ((float4*)dst)[i] = v;
}

// ---------------- patchify (stores pre-rounded: feeds GEMM A) ----------------
__global__ void __launch_bounds__(256)
patchify_kernel(const float* __restrict__ img)
{
    int idx = blockIdx.x * 256 + threadIdx.x;
    if (idx >= NP * IN_DIM) return;
    int t = idx / IN_DIM;
    int e = idx - t * IN_DIM;
    int n = t / PPATCH;
    int p = t - n * PPATCH;
    int py = p / 14, px = p - py * 14;
    int c  = e >> 8;
    int r  = e & 255;
    int ph = r >> 4, pw = r & 15;
    g_patches[idx] = tf32r(img[(((size_t)n * 3 + c) * 224 + (py * 16 + ph)) * 224 + px * 16 + pw]);
}

// ---------------- assemble (residual stream: full fp32) ----------------
__global__ void __launch_bounds__(256)
assemble_kernel(const float* __restrict__ tokens, const float* __restrict__ cls,
                const float* __restrict__ pos)
{
    int idx = blockIdx.x * 256 + threadIdx.x;
    if (idx >= NS * DMODEL) return;
    int t = idx / DMODEL;
    int d = idx - t * DMODEL;
    int n = t / SEQ;
    int s = t - n * SEQ;
    float v = (s == 0) ? cls[d] : tokens[((size_t)(n * PPATCH + s - 1)) * DMODEL + d];
    g_x[idx] = v + pos[s * DMODEL + d];
}

// ---------------- pipelined tf32 GEMM, cvt-free (operands pre-rounded) --------
// C = A@B + bias (+epilogue). Block 128x128, BK=32, 2-stage cp.async.
// EPI: 0 = bias, 1 = bias + exact GELU (output re-rounded to tf32), 2 = bias + residual
#define TG_SMEM ((2 * 128 * 36 + 2 * 32 * 132) * 4)   // 70656 bytes

template<int EPI>
__global__ void __launch_bounds__(256, 2)
tgemm128(const float* __restrict__ A, const float* __restrict__ B,
         const float* __restrict__ bias, const float* __restrict__ res,
         float* __restrict__ C, int M, int N, int K)
{
    extern __shared__ float smem[];
    float (*As)[128][36]  = reinterpret_cast<float(*)[128][36]>(smem);
    float (*Bs)[32][132]  = reinterpret_cast<float(*)[32][132]>(smem + 2 * 128 * 36);

    const int tid  = threadIdx.x;
    const int wid  = tid >> 5;
    const int lane = tid & 31;
    const int g    = lane >> 2;
    const int tig  = lane & 3;
    const int mw   = wid & 3;
    const int nw   = wid >> 2;
    const int bm   = blockIdx.y * 128;
    const int bn   = blockIdx.x * 128;

    float acc[2][8][4];
    #pragma unroll
    for (int i = 0; i < 2; i++)
        #pragma unroll
        for (int j = 0; j < 8; j++)
            #pragma unroll
            for (int c = 0; c < 4; c++) acc[i][j][c] = 0.f;

    auto load_tiles = [&](int kk0, int buf) {
        #pragma unroll
        for (int p = 0; p < 4; p++) {
            int idx = p * 256 + tid;
            int m   = idx >> 3;
            int c4  = (idx & 7) * 4;
            const float* src = A + (size_t)(bm + m) * K + kk0 + c4;
            uint32_t dst = (uint32_t)__cvta_generic_to_shared(&As[buf][m][c4]);
            int sz = (bm + m) < M ? 16 : 0;
            asm volatile("cp.async.cg.shared.global [%0], [%1], 16, %2;"
                         :: "r"(dst), "l"(src), "r"(sz) : "memory");
        }
        #pragma unroll
        for (int p = 0; p < 4; p++) {
            int idx = p * 256 + tid;
            int kr  = idx >> 5;
            int n4  = (idx & 31) * 4;
            const float* src = B + (size_t)(kk0 + kr) * N + bn + n4;
            uint32_t dst = (uint32_t)__cvta_generic_to_shared(&Bs[buf][kr][n4]);
            asm volatile("cp.async.cg.shared.global [%0], [%1], 16;"
                         :: "r"(dst), "l"(src) : "memory");
        }
        asm volatile("cp.async.commit_group;" ::: "memory");
    };

    const int T = K >> 5;
    load_tiles(0, 0);

    for (int kt = 0; kt < T; kt++) {
        const int buf = kt & 1;
        if (kt + 1 < T) {
            load_tiles((kt + 1) << 5, (kt + 1) & 1);
            asm volatile("cp.async.wait_group 1;" ::: "memory");
        } else {
            asm volatile("cp.async.wait_group 0;" ::: "memory");
        }
        __syncthreads();

        #pragma unroll
        for (int ks = 0; ks < 4; ks++) {
            const int kk = ks * 8;
            uint32_t af[2][4];
            #pragma unroll
            for (int mt = 0; mt < 2; mt++) {
                int rb = mw * 32 + mt * 16;
                af[mt][0] = __float_as_uint(As[buf][rb + g]    [kk + tig]);
                af[mt][1] = __float_as_uint(As[buf][rb + g + 8][kk + tig]);
                af[mt][2] = __float_as_uint(As[buf][rb + g]    [kk + tig + 4]);
                af[mt][3] = __float_as_uint(As[buf][rb + g + 8][kk + tig + 4]);
            }
            uint32_t bf[8][2];
            #pragma unroll
            for (int nt = 0; nt < 8; nt++) {
                int cb = nw * 64 + nt * 8 + g;
                bf[nt][0] = __float_as_uint(Bs[buf][kk + tig]    [cb]);
                bf[nt][1] = __float_as_uint(Bs[buf][kk + tig + 4][cb]);
            }
            #pragma unroll
            for (int mt = 0; mt < 2; mt++)
                #pragma unroll
                for (int nt = 0; nt < 8; nt++) {
                    asm volatile(
                        "mma.sync.aligned.m16n8k8.row.col.f32.tf32.tf32.f32 "
                        "{%0,%1,%2,%3},{%4,%5,%6,%7},{%8,%9},{%0,%1,%2,%3};"
                        : "+f"(acc[mt][nt][0]), "+f"(acc[mt][nt][1]),
                          "+f"(acc[mt][nt][2]), "+f"(acc[mt][nt][3])
                        : "r"(af[mt][0]), "r"(af[mt][1]), "r"(af[mt][2]), "r"(af[mt][3]),
                          "r"(bf[nt][0]), "r"(bf[nt][1]));
                }
        }
        __syncthreads();
    }

    // epilogue
    #pragma unroll
    for (int mt = 0; mt < 2; mt++) {
        int r0 = bm + mw * 32 + mt * 16 + g;
        int r1 = r0 + 8;
        #pragma unroll
        for (int nt = 0; nt < 8; nt++) {
            int c0 = bn + nw * 64 + nt * 8 + 2 * tig;
            float b0 = bias[c0], b1 = bias[c0 + 1];
            #pragma unroll
            for (int half = 0; half < 2; half++) {
                int row = half ? r1 : r0;
                if (row >= M) continue;
                float v0 = acc[mt][nt][half * 2 + 0] + b0;
                float v1 = acc[mt][nt][half * 2 + 1] + b1;
                if (EPI == 1) {
                    v0 = tf32r(0.5f * v0 * (1.f + erff(v0 * 0.70710678118654752f)));
                    v1 = tf32r(0.5f * v1 * (1.f + erff(v1 * 0.70710678118654752f)));
                }
                if (EPI == 2) {
                    const float2 rr = *(const float2*)(res + (size_t)row * N + c0);
                    v0 += rr.x; v1 += rr.y;
                }
                float2 o; o.x = v0; o.y = v1;
                *(float2*)(C + (size_t)row * N + c0) = o;
            }
        }
    }
}

// ---------------- LayerNorm (output pre-rounded: feeds GEMM/QKV A) ----------------
__global__ void __launch_bounds__(256)
ln_kernel(const float* __restrict__ x, const float* __restrict__ g,
          const float* __restrict__ b, float* __restrict__ o)
{
    int row = blockIdx.x;
    int tid = threadIdx.x;
    const float* xr = x + (size_t)row * DMODEL;
    float v0 = xr[tid], v1 = xr[tid + 256], v2 = xr[tid + 512];

    __shared__ float red[10];
    float s = v0 + v1 + v2;
    #pragma unroll
    for (int of = 16; of; of >>= 1) s += __shfl_xor_sync(~0u, s, of);
    if ((tid & 31) == 0) red[tid >> 5] = s;
    __syncthreads();
    if (tid == 0) {
        float t = 0.f;
        #pragma unroll
        for (int i = 0; i < 8; i++) t += red[i];
        red[8] = t * (1.f / 768.f);
    }
    __syncthreads();
    float mu = red[8];
    float d0 = v0 - mu, d1 = v1 - mu, d2 = v2 - mu;
    float q = d0 * d0 + d1 * d1 + d2 * d2;
    #pragma unroll
    for (int of = 16; of; of >>= 1) q += __shfl_xor_sync(~0u, q, of);
    if ((tid & 31) == 0) red[tid >> 5] = q;
    __syncthreads();
    if (tid == 0) {
        float t = 0.f;
        #pragma unroll
        for (int i = 0; i < 8; i++) t += red[i];
        red[9] = rsqrtf(t * (1.f / 768.f) + 1e-5f);
    }
    __syncthreads();
    float inv = red[9];
    float* orow = o + (size_t)row * DMODEL;
    orow[tid]       = tf32r(d0 * inv * g[tid]       + b[tid]);
    orow[tid + 256] = tf32r(d1 * inv * g[tid + 256] + b[tid + 256]);
    orow[tid + 512] = tf32r(d2 * inv * g[tid + 512] + b[tid + 512]);
}

// ---------------- per-head QKV projection ----------------
__global__ void __launch_bounds__(256)
qkv_kernel(const float* __restrict__ h,
           const float* __restrict__ Wq, const float* __restrict__ Wk, const float* __restrict__ Wv,
           const float* __restrict__ bq, const float* __restrict__ bk, const float* __restrict__ bv,
           float* __restrict__ q, float* __restrict__ k, float* __restrict__ v)
{
    int t0 = blockIdx.x * 64;
    int hh = blockIdx.y;
    int z  = blockIdx.z;
    const float* W  = (z == 0) ? Wq : (z == 1) ? Wk : Wv;
    const float* bb = (z == 0) ? bq : (z == 1) ? bk : bv;
    float* out      = (z == 0) ? q  : (z == 1) ? k  : v;
    W  += hh * 64 * 64;
    bb += hh * 64;

    __shared__ float Xs[64][64];
    __shared__ float Ws[64][64];
    int tid = threadIdx.x;
    #pragma unroll
    for (int r = 0; r < 4; r++) {
        int row = (tid >> 4) + r * 16;
        int col = (tid & 15) * 4;
        int tok = t0 + row;
        float4 xv = make_float4(0.f, 0.f, 0.f, 0.f);
        if (tok < NS) xv = *(const float4*)(h + (size_t)tok * DMODEL + hh * 64 + col);
        Xs[col + 0][row] = xv.x; Xs[col + 1][row] = xv.y;
        Xs[col + 2][row] = xv.z; Xs[col + 3][row] = xv.w;
        float4 wv = *(const float4*)(W + row * 64 + col);
        Ws[row][col + 0] = wv.x; Ws[row][col + 1] = wv.y;
        Ws[row][col + 2] = wv.z; Ws[row][col + 3] = wv.w;
    }
    __syncthreads();

    int trr = (tid >> 4) * 4;
    int tcc = (tid & 15) * 4;
    float acc[4][4] = {};
    #pragma unroll
    for (int d = 0; d < 64; d++) {
        float ra[4], rb[4];
        #pragma unroll
        for (int i = 0; i < 4; i++) ra[i] = Xs[d][trr + i];
        #pragma unroll
        for (int j = 0; j < 4; j++) rb[j] = Ws[d][tcc + j];
        #pragma unroll
        for (int i = 0; i < 4; i++)
            #pragma unroll
            for (int j = 0; j < 4; j++)
                acc[i][j] = fmaf(ra[i], rb[j], acc[i][j]);
    }
    #pragma unroll
    for (int i = 0; i < 4; i++) {
        int tok = t0 + trr + i;
        if (tok >= NS) continue;
        #pragma unroll
        for (int j = 0; j < 4; j++)
            out[(size_t)tok * DMODEL + hh * 64 + tcc + j] = acc[i][j] + bb[tcc + j];
    }
}

// ---------------- fused flash attention: O = softmax(QK^T/8) V, x += O ----------------
#define ATTN_SMEM (4 * 64 * 64 * 4)

__global__ void __launch_bounds__(256)
attn_kernel(const float* __restrict__ q, const float* __restrict__ k,
            const float* __restrict__ v, float* __restrict__ x)
{
    extern __shared__ float sm[];
    float (*Qs)[64] = reinterpret_cast<float(*)[64]>(sm);           // [e][q]
    float (*Ks)[64] = reinterpret_cast<float(*)[64]>(sm + 4096);    // [e][k]
    float (*Vs)[64] = reinterpret_cast<float(*)[64]>(sm + 8192);    // [k][e]
    float (*Ps)[64] = reinterpret_cast<float(*)[64]>(sm + 12288);   // [k][q]

    const int q0 = blockIdx.x * 64;
    const int b  = blockIdx.y;
    const int n  = b / NHEAD, hh = b - n * NHEAD;
    const int tid = threadIdx.x;
    const int tr = (tid >> 4) * 4;
    const int tc = (tid & 15) * 4;

    #pragma unroll
    for (int r = 0; r < 4; r++) {
        int row = (tid >> 4) + r * 16;
        int col = (tid & 15) * 4;
        int qt = q0 + row;
        float4 qv = make_float4(0.f, 0.f, 0.f, 0.f);
        if (qt < SEQ) qv = *(const float4*)(q + (size_t)(n * SEQ + qt) * DMODEL + hh * 64 + col);
        Qs[col + 0][row] = qv.x; Qs[col + 1][row] = qv.y;
        Qs[col + 2][row] = qv.z; Qs[col + 3][row] = qv.w;
    }

    float m_run[4], l_run[4], acc[4][4];
    #pragma unroll
    for (int i = 0; i < 4; i++) {
        m_run[i] = -1e30f; l_run[i] = 0.f;
        #pragma unroll
        for (int j = 0; j < 4; j++) acc[i][j] = 0.f;
    }

    for (int kt = 0; kt < 4; kt++) {
        const int k0 = kt * 64;
        __syncthreads();

        #pragma unroll
        for (int r = 0; r < 4; r++) {
            int row = (tid >> 4) + r * 16;
            int col = (tid & 15) * 4;
            int ktok = k0 + row;
            float4 kv = make_float4(0.f, 0.f, 0.f, 0.f);
            float4 vv = make_float4(0.f, 0.f, 0.f, 0.f);
            if (ktok < SEQ) {
                kv = *(const float4*)(k + (size_t)(n * SEQ + ktok) * DMODEL + hh * 64 + col);
                vv = *(const float4*)(v + (size_t)(n * SEQ + ktok) * DMODEL + hh * 64 + col);
            }
            Ks[col + 0][row] = kv.x; Ks[col + 1][row] = kv.y;
            Ks[col + 2][row] = kv.z; Ks[col + 3][row] = kv.w;
            Vs[row][col + 0] = vv.x; Vs[row][col + 1] = vv.y;
            Vs[row][col + 2] = vv.z; Vs[row][col + 3] = vv.w;
        }
        __syncthreads();

        float s[4][4] = {};
        #pragma unroll
        for (int e = 0; e < 64; e++) {
            float ra[4], rb[4];
            #pragma unroll
            for (int i = 0; i < 4; i++) ra[i] = Qs[e][tr + i];
            #pragma unroll
            for (int j = 0; j < 4; j++) rb[j] = Ks[e][tc + j];
            #pragma unroll
            for (int i = 0; i < 4; i++)
                #pragma unroll
                for (int j = 0; j < 4; j++)
                    s[i][j] = fmaf(ra[i], rb[j], s[i][j]);
        }
        #pragma unroll
        for (int i = 0; i < 4; i++)
            #pragma unroll
            for (int j = 0; j < 4; j++)
                s[i][j] = (k0 + tc + j < SEQ) ? s[i][j] * 0.125f : -1e30f;

        #pragma unroll
        for (int i = 0; i < 4; i++) {
            float mt_ = fmaxf(fmaxf(s[i][0], s[i][1]), fmaxf(s[i][2], s[i][3]));
            #pragma unroll
            for (int of = 1; of < 16; of <<= 1)
                mt_ = fmaxf(mt_, __shfl_xor_sync(~0u, mt_, of));
            float mnew = fmaxf(m_run[i], mt_);
            float sc = expf(m_run[i] - mnew);
            float rs = 0.f;
            #pragma unroll
            for (int j = 0; j < 4; j++) {
                float p = expf(s[i][j] - mnew);
                s[i][j] = p;
                rs += p;
            }
            #pragma unroll
            for (int of = 1; of < 16; of <<= 1)
                rs += __shfl_xor_sync(~0u, rs, of);
            l_run[i] = l_run[i] * sc + rs;
            #pragma unroll
            for (int j = 0; j < 4; j++) acc[i][j] *= sc;
            m_run[i] = mnew;
        }

        #pragma unroll
        for (int i = 0; i < 4; i++)
            #pragma unroll
            for (int j = 0; j < 4; j++)
                Ps[tc + j][tr + i] = s[i][j];
        __syncthreads();

        #pragma unroll
        for (int kk = 0; kk < 64; kk++) {
            float ra[4], rb[4];
            #pragma unroll
            for (int i = 0; i < 4; i++) ra[i] = Ps[kk][tr + i];
            #pragma unroll
            for (int j = 0; j < 4; j++) rb[j] = Vs[kk][tc + j];
            #pragma unroll
            for (int i = 0; i < 4; i++)
                #pragma unroll
                for (int j = 0; j < 4; j++)
                    acc[i][j] = fmaf(ra[i], rb[j], acc[i][j]);
        }
    }

    #pragma unroll
    for (int i = 0; i < 4; i++) {
        int qi = q0 + tr + i;
        if (qi >= SEQ) continue;
        float inv = 1.f / l_run[i];
        #pragma unroll
        for (int j = 0; j < 4; j++) {
            size_t idx = (size_t)(n * SEQ + qi) * DMODEL + hh * 64 + tc + j;
            x[idx] += acc[i][j] * inv;
        }
    }
}

// ---------------- head + softmax ----------------
__global__ void __launch_bounds__(256)
head_kernel(const float* __restrict__ x, const float* __restrict__ Wh,
            const float* __restrict__ bh, float* __restrict__ out)
{
    __shared__ float xs[DMODEL];
    __shared__ float lg[OUTD];
    __shared__ float red[256];
    int n = blockIdx.x, tid = threadIdx.x;
    for (int i = tid; i < DMODEL; i += 256) xs[i] = x[(size_t)n * SEQ * DMODEL + i];
    __syncthreads();
    for (int o = tid; o < OUTD; o += 256) {
        float a = bh[o];
        for (int kk = 0; kk < DMODEL; kk++)
            a = fmaf(xs[kk], Wh[(size_t)kk * OUTD + o], a);
        lg[o] = a;
    }
    __syncthreads();
    float m = -1e30f;
    for (int o = tid; o < OUTD; o += 256) m = fmaxf(m, lg[o]);
    red[tid] = m; __syncthreads();
    for (int s = 128; s; s >>= 1) { if (tid < s) red[tid] = fmaxf(red[tid], red[tid + s]); __syncthreads(); }
    float mx = red[0]; __syncthreads();
    float sm = 0.f;
    for (int o = tid; o < OUTD; o += 256) sm += expf(lg[o] - mx);
    red[tid] = sm; __syncthreads();
    for (int s = 128; s; s >>= 1) { if (tid < s) red[tid] += red[tid + s]; __syncthreads(); }
    float inv = 1.f / red[0];
    __syncthreads();
    for (int o = tid; o < OUTD; o += 256)
        out[(size_t)n * OUTD + o] = expf(lg[o] - mx) * inv;
}

// ---------------- host orchestration ----------------
extern "C" void kernel_launch(void* const* d_in, const int* in_sizes, int n_in,
                              void* d_out, int out_size)
{
    const float* images   = (const float*)d_in[0];
    const float* W_map    = (const float*)d_in[1];
    const float* b_map    = (const float*)d_in[2];
    const float* cls      = (const float*)d_in[3];
    const float* pos      = (const float*)d_in[4];
    const float* ln1_g    = (const float*)d_in[5];
    const float* ln1_b    = (const float*)d_in[6];
    const float* Wq       = (const float*)d_in[7];
    const float* bq       = (const float*)d_in[8];
    const float* Wk       = (const float*)d_in[9];
    const float* bk       = (const float*)d_in[10];
    const float* Wv       = (const float*)d_in[11];
    const float* bv       = (const float*)d_in[12];
    const float* ln2_g    = (const float*)d_in[13];
    const float* ln2_b    = (const float*)d_in[14];
    const float* W1       = (const float*)d_in[15];
    const float* b1       = (const float*)d_in[16];
    const float* W2       = (const float*)d_in[17];
    const float* b2       = (const float*)d_in[18];
    const float* W_head   = (const float*)d_in[19];
    const float* b_head   = (const float*)d_in[20];
    float* out = (float*)d_out;

    float *p_patches, *p_x, *p_h, *p_q, *p_k, *p_v, *p_mlp;
    float *p_wmap, *p_w1, *p_w2;
    cudaGetSymbolAddress((void**)&p_patches, g_patches);
    cudaGetSymbolAddress((void**)&p_x, g_x);
    cudaGetSymbolAddress((void**)&p_h, g_h);
    cudaGetSymbolAddress((void**)&p_q, g_q);
    cudaGetSymbolAddress((void**)&p_k, g_k);
    cudaGetSymbolAddress((void**)&p_v, g_v);
    cudaGetSymbolAddress((void**)&p_mlp, g_mlp);
    cudaGetSymbolAddress((void**)&p_wmap, g_wmap);
    cudaGetSymbolAddress((void**)&p_w1, g_w1);
    cudaGetSymbolAddress((void**)&p_w2, g_w2);

    cudaFuncSetAttribute(tgemm128<0>, cudaFuncAttributeMaxDynamicSharedMemorySize, TG_SMEM);
    cudaFuncSetAttribute(tgemm128<1>, cudaFuncAttributeMaxDynamicSharedMemorySize, TG_SMEM);
    cudaFuncSetAttribute(tgemm128<2>, cudaFuncAttributeMaxDynamicSharedMemorySize, TG_SMEM);
    cudaFuncSetAttribute(attn_kernel, cudaFuncAttributeMaxDynamicSharedMemorySize, ATTN_SMEM);

    // 0) pre-round weights to tf32 (RNA) once per launch
    cvt_kernel<<<(IN_DIM * DMODEL / 4 + 255) / 256, 256>>>(W_map, p_wmap, IN_DIM * DMODEL / 4);
    cvt_kernel<<<(LAYERS * DMODEL * MLPD / 4 + 255) / 256, 256>>>(W1, p_w1, LAYERS * DMODEL * MLPD / 4);
    cvt_kernel<<<(LAYERS * MLPD * DMODEL / 4 + 255) / 256, 256>>>(W2, p_w2, LAYERS * MLPD * DMODEL / 4);

    // 1) patchify + embed + assemble
    patchify_kernel<<<(NP * IN_DIM) / 256, 256>>>(images);
    {
        dim3 grid(DMODEL / 128, NP / 128);   // 6 x 49
        tgemm128<0><<<grid, 256, TG_SMEM>>>(p_patches, p_wmap, b_map, nullptr, p_mlp,
                                            NP, DMODEL, IN_DIM);
    }
    assemble_kernel<<<(NS * DMODEL) / 256, 256>>>(p_mlp, cls, pos);

    // 2) transformer blocks
    for (int l = 0; l < LAYERS; l++) {
        ln_kernel<<<NS, 256>>>(p_x, ln1_g + l * DMODEL, ln1_b + l * DMODEL, p_h);

        {
            dim3 grid((NS + 63) / 64, NHEAD, 3);
            qkv_kernel<<<grid, 256>>>(p_h,
                Wq + (size_t)l * NHEAD * DHEAD * DHEAD,
                Wk + (size_t)l * NHEAD * DHEAD * DHEAD,
                Wv + (size_t)l * NHEAD * DHEAD * DHEAD,
                bq + (size_t)l * NHEAD * DHEAD,
                bk + (size_t)l * NHEAD * DHEAD,
                bv + (size_t)l * NHEAD * DHEAD,
                p_q, p_k, p_v);
        }
        {
            dim3 grid((SEQ + 63) / 64, NB * NHEAD);   // 4 x 384
            attn_kernel<<<grid, 256, ATTN_SMEM>>>(p_q, p_k, p_v, p_x);
        }

        ln_kernel<<<NS, 256>>>(p_x, ln2_g + l * DMODEL, ln2_b + l * DMODEL, p_h);
        {
            dim3 grid(MLPD / 128, (NS + 127) / 128);   // 24 x 50
            tgemm128<1><<<grid, 256, TG_SMEM>>>(p_h, p_w1 + (size_t)l * DMODEL * MLPD,
                                                b1 + (size_t)l * MLPD, nullptr, p_mlp,
                                                NS, MLPD, DMODEL);
        }
        {
            dim3 grid(DMODEL / 128, (NS + 127) / 128); // 6 x 50
            tgemm128<2><<<grid, 256, TG_SMEM>>>(p_mlp, p_w2 + (size_t)l * MLPD * DMODEL,
                                                b2 + (size_t)l * DMODEL, p_x, p_x,
                                                NS, DMODEL, MLPD);
        }
    }

    // 3) head + softmax
    head_kernel<<<NB, 256>>>(p_x, W_head, b_head, out);
}

// round 7
// speedup vs baseline: 2.3198x; 1.3799x over previous
#include <cuda_runtime.h>
#include <cuda_bf16.h>
#include <math.h>
#include <cstdint>

// ---------------- problem constants ----------------
#define NB     32
#define SEQ    197
#define DMODEL 768
#define NHEAD  12
#define DHEAD  64
#define LAYERS 12
#define MLPD   3072
#define OUTD   1000
#define PPATCH 196
#define IN_DIM 768
#define NS     (NB * SEQ)       // 6304 tokens
#define NP     (NB * PPATCH)    // 6272 patches

// ---------------- device scratch ----------------
__device__ float g_patches[NP * IN_DIM];
__device__ float g_x[NS * DMODEL];
__device__ float g_h[NS * DMODEL];
__device__ float g_q[NS * DMODEL];
__device__ float g_k[NS * DMODEL];
__device__ float g_v[NS * DMODEL];
__device__ float g_mlp[NS * MLPD];
// pre-rounded (tf32 RNA) weight copies
__device__ float g_wmap[IN_DIM * DMODEL];
__device__ float g_w1[LAYERS * DMODEL * MLPD];
__device__ float g_w2[LAYERS * MLPD * DMODEL];
__device__ float g_wq[LAYERS * NHEAD * DHEAD * DHEAD];
__device__ float g_wk[LAYERS * NHEAD * DHEAD * DHEAD];
__device__ float g_wv[LAYERS * NHEAD * DHEAD * DHEAD];

__device__ __forceinline__ float tf32r(float x)
{
    float r;
    asm("cvt.rna.tf32.f32 %0, %1;" : "=f"(r) : "f"(x));
    return r;
}

__device__ __forceinline__ void mma_tf32(float* c, uint32_t a0, uint32_t a1,
                                         uint32_t a2, uint32_t a3,
                                         uint32_t b0, uint32_t b1)
{
    asm volatile(
        "mma.sync.aligned.m16n8k8.row.col.f32.tf32.tf32.f32 "
        "{%0,%1,%2,%3},{%4,%5,%6,%7},{%8,%9},{%0,%1,%2,%3};"
        : "+f"(c[0]), "+f"(c[1]), "+f"(c[2]), "+f"(c[3])
        : "r"(a0), "r"(a1), "r"(a2), "r"(a3), "r"(b0), "r"(b1));
}

// ---------------- weight pre-rounding ----------------
__global__ void __launch_bounds__(256)
cvt_kernel(const float* __restrict__ src, float* __restrict__ dst, int n4)
{
    int i = blockIdx.x * 256 + threadIdx.x;
    if (i >= n4) return;
    float4 v = ((const float4*)src)[i];
    v.x = tf32r(v.x); v.y = tf32r(v.y); v.z = tf32r(v.z); v.w = tf32r(v.w);
    ((float4*)dst)[i] = v;
}

// ---------------- patchify (pre-rounded: feeds GEMM A) ----------------
__global__ void __launch_bounds__(256)
patchify_kernel(const float* __restrict__ img)
{
    int idx = blockIdx.x * 256 + threadIdx.x;
    if (idx >= NP * IN_DIM) return;
    int t = idx / IN_DIM;
    int e = idx - t * IN_DIM;
    int n = t / PPATCH;
    int p = t - n * PPATCH;
    int py = p / 14, px = p - py * 14;
    int c  = e >> 8;
    int r  = e & 255;
    int ph = r >> 4, pw = r & 15;
    g_patches[idx] = tf32r(img[(((size_t)n * 3 + c) * 224 + (py * 16 + ph)) * 224 + px * 16 + pw]);
}

// ---------------- assemble ----------------
__global__ void __launch_bounds__(256)
assemble_kernel(const float* __restrict__ tokens, const float* __restrict__ cls,
                const float* __restrict__ pos)
{
    int idx = blockIdx.x * 256 + threadIdx.x;
    if (idx >= NS * DMODEL) return;
    int t = idx / DMODEL;
    int d = idx - t * DMODEL;
    int n = t / SEQ;
    int s = t - n * SEQ;
    float v = (s == 0) ? cls[d] : tokens[((size_t)(n * PPATCH + s - 1)) * DMODEL + d];
    g_x[idx] = v + pos[s * DMODEL + d];
}

// ---------------- pipelined tf32 GEMM (cvt-free) ----------------
#define TG_SMEM ((2 * 128 * 36 + 2 * 32 * 132) * 4)   // 70656 bytes

template<int EPI>
__global__ void __launch_bounds__(256, 2)
tgemm128(const float* __restrict__ A, const float* __restrict__ B,
         const float* __restrict__ bias, const float* __restrict__ res,
         float* __restrict__ C, int M, int N, int K)
{
    extern __shared__ float smem[];
    float (*As)[128][36]  = reinterpret_cast<float(*)[128][36]>(smem);
    float (*Bs)[32][132]  = reinterpret_cast<float(*)[32][132]>(smem + 2 * 128 * 36);

    const int tid  = threadIdx.x;
    const int wid  = tid >> 5;
    const int lane = tid & 31;
    const int g    = lane >> 2;
    const int tig  = lane & 3;
    const int mw   = wid & 3;
    const int nw   = wid >> 2;
    const int bm   = blockIdx.y * 128;
    const int bn   = blockIdx.x * 128;

    float acc[2][8][4];
    #pragma unroll
    for (int i = 0; i < 2; i++)
        #pragma unroll
        for (int j = 0; j < 8; j++)
            #pragma unroll
            for (int c = 0; c < 4; c++) acc[i][j][c] = 0.f;

    auto load_tiles = [&](int kk0, int buf) {
        #pragma unroll
        for (int p = 0; p < 4; p++) {
            int idx = p * 256 + tid;
            int m   = idx >> 3;
            int c4  = (idx & 7) * 4;
            const float* src = A + (size_t)(bm + m) * K + kk0 + c4;
            uint32_t dst = (uint32_t)__cvta_generic_to_shared(&As[buf][m][c4]);
            int sz = (bm + m) < M ? 16 : 0;
            asm volatile("cp.async.cg.shared.global [%0], [%1], 16, %2;"
                         :: "r"(dst), "l"(src), "r"(sz) : "memory");
        }
        #pragma unroll
        for (int p = 0; p < 4; p++) {
            int idx = p * 256 + tid;
            int kr  = idx >> 5;
            int n4  = (idx & 31) * 4;
            const float* src = B + (size_t)(kk0 + kr) * N + bn + n4;
            uint32_t dst = (uint32_t)__cvta_generic_to_shared(&Bs[buf][kr][n4]);
            asm volatile("cp.async.cg.shared.global [%0], [%1], 16;"
                         :: "r"(dst), "l"(src) : "memory");
        }
        asm volatile("cp.async.commit_group;" ::: "memory");
    };

    const int T = K >> 5;
    load_tiles(0, 0);

    for (int kt = 0; kt < T; kt++) {
        const int buf = kt & 1;
        if (kt + 1 < T) {
            load_tiles((kt + 1) << 5, (kt + 1) & 1);
            asm volatile("cp.async.wait_group 1;" ::: "memory");
        } else {
            asm volatile("cp.async.wait_group 0;" ::: "memory");
        }
        __syncthreads();

        #pragma unroll
        for (int ks = 0; ks < 4; ks++) {
            const int kk = ks * 8;
            uint32_t af[2][4];
            #pragma unroll
            for (int mt = 0; mt < 2; mt++) {
                int rb = mw * 32 + mt * 16;
                af[mt][0] = __float_as_uint(As[buf][rb + g]    [kk + tig]);
                af[mt][1] = __float_as_uint(As[buf][rb + g + 8][kk + tig]);
                af[mt][2] = __float_as_uint(As[buf][rb + g]    [kk + tig + 4]);
                af[mt][3] = __float_as_uint(As[buf][rb + g + 8][kk + tig + 4]);
            }
            uint32_t bf[8][2];
            #pragma unroll
            for (int nt = 0; nt < 8; nt++) {
                int cb = nw * 64 + nt * 8 + g;
                bf[nt][0] = __float_as_uint(Bs[buf][kk + tig]    [cb]);
                bf[nt][1] = __float_as_uint(Bs[buf][kk + tig + 4][cb]);
            }
            #pragma unroll
            for (int mt = 0; mt < 2; mt++)
                #pragma unroll
                for (int nt = 0; nt < 8; nt++)
                    mma_tf32(acc[mt][nt], af[mt][0], af[mt][1], af[mt][2], af[mt][3],
                             bf[nt][0], bf[nt][1]);
        }
        __syncthreads();
    }

    #pragma unroll
    for (int mt = 0; mt < 2; mt++) {
        int r0 = bm + mw * 32 + mt * 16 + g;
        int r1 = r0 + 8;
        #pragma unroll
        for (int nt = 0; nt < 8; nt++) {
            int c0 = bn + nw * 64 + nt * 8 + 2 * tig;
            float b0 = bias[c0], b1 = bias[c0 + 1];
            #pragma unroll
            for (int half = 0; half < 2; half++) {
                int row = half ? r1 : r0;
                if (row >= M) continue;
                float v0 = acc[mt][nt][half * 2 + 0] + b0;
                float v1 = acc[mt][nt][half * 2 + 1] + b1;
                if (EPI == 1) {
                    v0 = tf32r(0.5f * v0 * (1.f + erff(v0 * 0.70710678118654752f)));
                    v1 = tf32r(0.5f * v1 * (1.f + erff(v1 * 0.70710678118654752f)));
                }
                if (EPI == 2) {
                    const float2 rr = *(const float2*)(res + (size_t)row * N + c0);
                    v0 += rr.x; v1 += rr.y;
                }
                float2 o; o.x = v0; o.y = v1;
                *(float2*)(C + (size_t)row * N + c0) = o;
            }
        }
    }
}

// ---------------- LayerNorm (output pre-rounded) ----------------
__global__ void __launch_bounds__(256)
ln_kernel(const float* __restrict__ x, const float* __restrict__ g,
          const float* __restrict__ b, float* __restrict__ o)
{
    int row = blockIdx.x;
    int tid = threadIdx.x;
    const float* xr = x + (size_t)row * DMODEL;
    float v0 = xr[tid], v1 = xr[tid + 256], v2 = xr[tid + 512];

    __shared__ float red[10];
    float s = v0 + v1 + v2;
    #pragma unroll
    for (int of = 16; of; of >>= 1) s += __shfl_xor_sync(~0u, s, of);
    if ((tid & 31) == 0) red[tid >> 5] = s;
    __syncthreads();
    if (tid == 0) {
        float t = 0.f;
        #pragma unroll
        for (int i = 0; i < 8; i++) t += red[i];
        red[8] = t * (1.f / 768.f);
    }
    __syncthreads();
    float mu = red[8];
    float d0 = v0 - mu, d1 = v1 - mu, d2 = v2 - mu;
    float q = d0 * d0 + d1 * d1 + d2 * d2;
    #pragma unroll
    for (int of = 16; of; of >>= 1) q += __shfl_xor_sync(~0u, q, of);
    if ((tid & 31) == 0) red[tid >> 5] = q;
    __syncthreads();
    if (tid == 0) {
        float t = 0.f;
        #pragma unroll
        for (int i = 0; i < 8; i++) t += red[i];
        red[9] = rsqrtf(t * (1.f / 768.f) + 1e-5f);
    }
    __syncthreads();
    float inv = red[9];
    float* orow = o + (size_t)row * DMODEL;
    orow[tid]       = tf32r(d0 * inv * g[tid]       + b[tid]);
    orow[tid + 256] = tf32r(d1 * inv * g[tid + 256] + b[tid + 256]);
    orow[tid + 512] = tf32r(d2 * inv * g[tid + 512] + b[tid + 512]);
}

// ---------------- per-head QKV projection, tf32 mma ----------------
// Block 128 threads (4 warps), tile 64 tokens x 64 out-dims, K=64.
__global__ void __launch_bounds__(128)
qkv_kernel(const float* __restrict__ h,
           const float* __restrict__ Wq, const float* __restrict__ Wk, const float* __restrict__ Wv,
           const float* __restrict__ bq, const float* __restrict__ bk, const float* __restrict__ bv,
           float* __restrict__ q, float* __restrict__ k, float* __restrict__ v)
{
    __shared__ float Xs[64][68];   // [token][d]
    __shared__ float Ws[64][68];   // [d][e]

    const int t0 = blockIdx.x * 64;
    const int hh = blockIdx.y;
    const int z  = blockIdx.z;
    const float* W  = ((z == 0) ? Wq : (z == 1) ? Wk : Wv) + hh * 64 * 64;
    const float* bb = ((z == 0) ? bq : (z == 1) ? bk : bv) + hh * 64;
    float* out      = (z == 0) ? q  : (z == 1) ? k  : v;

    const int tid  = threadIdx.x;
    const int wid  = tid >> 5;
    const int lane = tid & 31;
    const int g    = lane >> 2;
    const int tig  = lane & 3;
    const int rb   = wid * 16;

    #pragma unroll
    for (int it = 0; it < 8; it++) {
        int idx = it * 128 + tid;
        int row = idx >> 4;
        int col = (idx & 15) * 4;
        int tok = t0 + row;
        float4 xv = make_float4(0.f, 0.f, 0.f, 0.f);
        if (tok < NS) xv = *(const float4*)(h + (size_t)tok * DMODEL + hh * 64 + col);
        *(float4*)&Xs[row][col] = xv;
        *(float4*)&Ws[row][col] = *(const float4*)(W + row * 64 + col);
    }
    __syncthreads();

    float acc[8][4];
    #pragma unroll
    for (int nt = 0; nt < 8; nt++)
        #pragma unroll
        for (int c = 0; c < 4; c++) acc[nt][c] = 0.f;

    #pragma unroll
    for (int ks = 0; ks < 8; ks++) {
        const int kk = ks * 8;
        uint32_t a0 = __float_as_uint(Xs[rb + g]    [kk + tig]);
        uint32_t a1 = __float_as_uint(Xs[rb + g + 8][kk + tig]);
        uint32_t a2 = __float_as_uint(Xs[rb + g]    [kk + tig + 4]);
        uint32_t a3 = __float_as_uint(Xs[rb + g + 8][kk + tig + 4]);
        #pragma unroll
        for (int nt = 0; nt < 8; nt++) {
            uint32_t b0 = __float_as_uint(Ws[kk + tig]    [nt * 8 + g]);
            uint32_t b1 = __float_as_uint(Ws[kk + tig + 4][nt * 8 + g]);
            mma_tf32(acc[nt], a0, a1, a2, a3, b0, b1);
        }
    }

    #pragma unroll
    for (int nt = 0; nt < 8; nt++) {
        int col = nt * 8 + 2 * tig;
        float b0 = bb[col], b1 = bb[col + 1];
        #pragma unroll
        for (int half = 0; half < 2; half++) {
            int tok = t0 + rb + g + half * 8;
            if (tok >= NS) continue;
            float2 o;
            o.x = tf32r(acc[nt][half * 2 + 0] + b0);
            o.y = tf32r(acc[nt][half * 2 + 1] + b1);
            *(float2*)(out + (size_t)tok * DMODEL + hh * 64 + col) = o;
        }
    }
}

// ---------------- fused flash attention, tf32 mma ----------------
// Block 128 threads (4 warps), 64 queries; warp owns 16 q rows.
#define ATTN_SMEM ((3 * 64 * 68 + 64 * 72) * 4)   // 70656 bytes

__global__ void __launch_bounds__(128)
attn_kernel(const float* __restrict__ q, const float* __restrict__ k,
            const float* __restrict__ v, float* __restrict__ x)
{
    extern __shared__ float sm[];
    float (*Qs)[68] = reinterpret_cast<float(*)[68]>(sm);                 // [q][d]
    float (*Ks)[68] = reinterpret_cast<float(*)[68]>(sm + 64 * 68);      // [key][d]
    float (*Ps)[68] = reinterpret_cast<float(*)[68]>(sm + 2 * 64 * 68);  // [q][key]
    float (*Vs)[72] = reinterpret_cast<float(*)[72]>(sm + 3 * 64 * 68);  // [key][e]

    const int q0 = blockIdx.x * 64;
    const int b  = blockIdx.y;
    const int n  = b / NHEAD, hh = b - n * NHEAD;
    const int tid  = threadIdx.x;
    const int wid  = tid >> 5;
    const int lane = tid & 31;
    const int g    = lane >> 2;
    const int tig  = lane & 3;
    const int rb   = wid * 16;

    // load Q tile (natural layout)
    #pragma unroll
    for (int it = 0; it < 8; it++) {
        int idx = it * 128 + tid;
        int row = idx >> 4;
        int col = (idx & 15) * 4;
        int qt = q0 + row;
        float4 qv = make_float4(0.f, 0.f, 0.f, 0.f);
        if (qt < SEQ) qv = *(const float4*)(q + (size_t)(n * SEQ + qt) * DMODEL + hh * 64 + col);
        *(float4*)&Qs[row][col] = qv;
    }

    float m_run[2] = {-1e30f, -1e30f};
    float l_run[2] = {0.f, 0.f};
    float acc_o[8][4];
    #pragma unroll
    for (int nt = 0; nt < 8; nt++)
        #pragma unroll
        for (int c = 0; c < 4; c++) acc_o[nt][c] = 0.f;

    for (int kt = 0; kt < 4; kt++) {
        const int k0 = kt * 64;
        __syncthreads();

        // load K, V tiles (natural layout)
        #pragma unroll
        for (int it = 0; it < 8; it++) {
            int idx = it * 128 + tid;
            int row = idx >> 4;
            int col = (idx & 15) * 4;
            int ktok = k0 + row;
            float4 kv = make_float4(0.f, 0.f, 0.f, 0.f);
            float4 vv = make_float4(0.f, 0.f, 0.f, 0.f);
            if (ktok < SEQ) {
                kv = *(const float4*)(k + (size_t)(n * SEQ + ktok) * DMODEL + hh * 64 + col);
                vv = *(const float4*)(v + (size_t)(n * SEQ + ktok) * DMODEL + hh * 64 + col);
            }
            *(float4*)&Ks[row][col] = kv;
            *(float4*)&Vs[row][col] = vv;
        }
        __syncthreads();

        // S = Q K^T  (warp: 16 q rows x 64 keys)
        float s[8][4];
        #pragma unroll
        for (int nt = 0; nt < 8; nt++)
            #pragma unroll
            for (int c = 0; c < 4; c++) s[nt][c] = 0.f;

        #pragma unroll
        for (int ks = 0; ks < 8; ks++) {
            const int kk = ks * 8;
            uint32_t a0 = __float_as_uint(Qs[rb + g]    [kk + tig]);
            uint32_t a1 = __float_as_uint(Qs[rb + g + 8][kk + tig]);
            uint32_t a2 = __float_as_uint(Qs[rb + g]    [kk + tig + 4]);
            uint32_t a3 = __float_as_uint(Qs[rb + g + 8][kk + tig + 4]);
            #pragma unroll
            for (int nt = 0; nt < 8; nt++) {
                uint32_t b0 = __float_as_uint(Ks[nt * 8 + g][kk + tig]);
                uint32_t b1 = __float_as_uint(Ks[nt * 8 + g][kk + tig + 4]);
                mma_tf32(s[nt], a0, a1, a2, a3, b0, b1);
            }
        }

        // scale + key mask (cols = nt*8 + 2tig + {0,1})
        #pragma unroll
        for (int nt = 0; nt < 8; nt++) {
            int c0 = k0 + nt * 8 + 2 * tig;
            s[nt][0] = (c0     < SEQ) ? s[nt][0] * 0.125f : -1e30f;
            s[nt][1] = (c0 + 1 < SEQ) ? s[nt][1] * 0.125f : -1e30f;
            s[nt][2] = (c0     < SEQ) ? s[nt][2] * 0.125f : -1e30f;
            s[nt][3] = (c0 + 1 < SEQ) ? s[nt][3] * 0.125f : -1e30f;
        }

        // online softmax per row pair (row0 = rb+g: c0,c1; row1 = rb+g+8: c2,c3)
        #pragma unroll
        for (int r = 0; r < 2; r++) {
            float mt_ = -1e30f;
            #pragma unroll
            for (int nt = 0; nt < 8; nt++)
                mt_ = fmaxf(mt_, fmaxf(s[nt][2 * r], s[nt][2 * r + 1]));
            mt_ = fmaxf(mt_, __shfl_xor_sync(~0u, mt_, 1));
            mt_ = fmaxf(mt_, __shfl_xor_sync(~0u, mt_, 2));
            float mnew = fmaxf(m_run[r], mt_);
            float sc = expf(m_run[r] - mnew);
            float rs = 0.f;
            #pragma unroll
            for (int nt = 0; nt < 8; nt++) {
                float p0 = expf(s[nt][2 * r]     - mnew);
                float p1 = expf(s[nt][2 * r + 1] - mnew);
                s[nt][2 * r] = p0; s[nt][2 * r + 1] = p1;
                rs += p0 + p1;
            }
            rs += __shfl_xor_sync(~0u, rs, 1);
            rs += __shfl_xor_sync(~0u, rs, 2);
            l_run[r] = l_run[r] * sc + rs;
            #pragma unroll
            for (int nt = 0; nt < 8; nt++) {
                acc_o[nt][2 * r]     *= sc;
                acc_o[nt][2 * r + 1] *= sc;
            }
            m_run[r] = mnew;
        }

        // stage P (tf32-rounded) -> Ps[q][key]; warp-local rows
        #pragma unroll
        for (int nt = 0; nt < 8; nt++) {
            float2 p0; p0.x = tf32r(s[nt][0]); p0.y = tf32r(s[nt][1]);
            float2 p1; p1.x = tf32r(s[nt][2]); p1.y = tf32r(s[nt][3]);
            *(float2*)&Ps[rb + g]    [nt * 8 + 2 * tig] = p0;
            *(float2*)&Ps[rb + g + 8][nt * 8 + 2 * tig] = p1;
        }
        __syncwarp();

        // O += P @ V
        #pragma unroll
        for (int ks = 0; ks < 8; ks++) {
            const int kk = ks * 8;
            uint32_t a0 = __float_as_uint(Ps[rb + g]    [kk + tig]);
            uint32_t a1 = __float_as_uint(Ps[rb + g + 8][kk + tig]);
            uint32_t a2 = __float_as_uint(Ps[rb + g]    [kk + tig + 4]);
            uint32_t a3 = __float_as_uint(Ps[rb + g + 8][kk + tig + 4]);
            #pragma unroll
            for (int nt = 0; nt < 8; nt++) {
                uint32_t b0 = __float_as_uint(Vs[kk + tig]    [nt * 8 + g]);
                uint32_t b1 = __float_as_uint(Vs[kk + tig + 4][nt * 8 + g]);
                mma_tf32(acc_o[nt], a0, a1, a2, a3, b0, b1);
            }
        }
    }

    // epilogue: x += O / l
    #pragma unroll
    for (int r = 0; r < 2; r++) {
        int row = q0 + rb + g + r * 8;
        if (row >= SEQ) continue;
        float inv = 1.f / l_run[r];
        #pragma unroll
        for (int nt = 0; nt < 8; nt++) {
            int col = hh * 64 + nt * 8 + 2 * tig;
            float* px = x + (size_t)(n * SEQ + row) * DMODEL + col;
            float2 old = *(float2*)px;
            old.x += acc_o[nt][2 * r]     * inv;
            old.y += acc_o[nt][2 * r + 1] * inv;
            *(float2*)px = old;
        }
    }
}

// ---------------- head + softmax ----------------
__global__ void __launch_bounds__(256)
head_kernel(const float* __restrict__ x, const float* __restrict__ Wh,
            const float* __restrict__ bh, float* __restrict__ out)
{
    __shared__ float xs[DMODEL];
    __shared__ float lg[OUTD];
    __shared__ float red[256];
    int n = blockIdx.x, tid = threadIdx.x;
    for (int i = tid; i < DMODEL; i += 256) xs[i] = x[(size_t)n * SEQ * DMODEL + i];
    __syncthreads();
    for (int o = tid; o < OUTD; o += 256) {
        float a = bh[o];
        for (int kk = 0; kk < DMODEL; kk++)
            a = fmaf(xs[kk], Wh[(size_t)kk * OUTD + o], a);
        lg[o] = a;
    }
    __syncthreads();
    float m = -1e30f;
    for (int o = tid; o < OUTD; o += 256) m = fmaxf(m, lg[o]);
    red[tid] = m; __syncthreads();
    for (int s = 128; s; s >>= 1) { if (tid < s) red[tid] = fmaxf(red[tid], red[tid + s]); __syncthreads(); }
    float mx = red[0]; __syncthreads();
    float sm = 0.f;
    for (int o = tid; o < OUTD; o += 256) sm += expf(lg[o] - mx);
    red[tid] = sm; __syncthreads();
    for (int s = 128; s; s >>= 1) { if (tid < s) red[tid] += red[tid + s]; __syncthreads(); }
    float inv = 1.f / red[0];
    __syncthreads();
    for (int o = tid; o < OUTD; o += 256)
        out[(size_t)n * OUTD + o] = expf(lg[o] - mx) * inv;
}

// ---------------- host orchestration ----------------
extern "C" void kernel_launch(void* const* d_in, const int* in_sizes, int n_in,
                              void* d_out, int out_size)
{
    const float* images   = (const float*)d_in[0];
    const float* W_map    = (const float*)d_in[1];
    const float* b_map    = (const float*)d_in[2];
    const float* cls      = (const float*)d_in[3];
    const float* pos      = (const float*)d_in[4];
    const float* ln1_g    = (const float*)d_in[5];
    const float* ln1_b    = (const float*)d_in[6];
    const float* Wq       = (const float*)d_in[7];
    const float* bq       = (const float*)d_in[8];
    const float* Wk       = (const float*)d_in[9];
    const float* bk       = (const float*)d_in[10];
    const float* Wv       = (const float*)d_in[11];
    const float* bv       = (const float*)d_in[12];
    const float* ln2_g    = (const float*)d_in[13];
    const float* ln2_b    = (const float*)d_in[14];
    const float* W1       = (const float*)d_in[15];
    const float* b1       = (const float*)d_in[16];
    const float* W2       = (const float*)d_in[17];
    const float* b2       = (const float*)d_in[18];
    const float* W_head   = (const float*)d_in[19];
    const float* b_head   = (const float*)d_in[20];
    float* out = (float*)d_out;

    float *p_patches, *p_x, *p_h, *p_q, *p_k, *p_v, *p_mlp;
    float *p_wmap, *p_w1, *p_w2, *p_wq, *p_wk, *p_wv;
    cudaGetSymbolAddress((void**)&p_patches, g_patches);
    cudaGetSymbolAddress((void**)&p_x, g_x);
    cudaGetSymbolAddress((void**)&p_h, g_h);
    cudaGetSymbolAddress((void**)&p_q, g_q);
    cudaGetSymbolAddress((void**)&p_k, g_k);
    cudaGetSymbolAddress((void**)&p_v, g_v);
    cudaGetSymbolAddress((void**)&p_mlp, g_mlp);
    cudaGetSymbolAddress((void**)&p_wmap, g_wmap);
    cudaGetSymbolAddress((void**)&p_w1, g_w1);
    cudaGetSymbolAddress((void**)&p_w2, g_w2);
    cudaGetSymbolAddress((void**)&p_wq, g_wq);
    cudaGetSymbolAddress((void**)&p_wk, g_wk);
    cudaGetSymbolAddress((void**)&p_wv, g_wv);

    cudaFuncSetAttribute(tgemm128<0>, cudaFuncAttributeMaxDynamicSharedMemorySize, TG_SMEM);
    cudaFuncSetAttribute(tgemm128<1>, cudaFuncAttributeMaxDynamicSharedMemorySize, TG_SMEM);
    cudaFuncSetAttribute(tgemm128<2>, cudaFuncAttributeMaxDynamicSharedMemorySize, TG_SMEM);
    cudaFuncSetAttribute(attn_kernel, cudaFuncAttributeMaxDynamicSharedMemorySize, ATTN_SMEM);

    // 0) pre-round weights to tf32 (RNA)
    cvt_kernel<<<(IN_DIM * DMODEL / 4 + 255) / 256, 256>>>(W_map, p_wmap, IN_DIM * DMODEL / 4);
    cvt_kernel<<<(LAYERS * DMODEL * MLPD / 4 + 255) / 256, 256>>>(W1, p_w1, LAYERS * DMODEL * MLPD / 4);
    cvt_kernel<<<(LAYERS * MLPD * DMODEL / 4 + 255) / 256, 256>>>(W2, p_w2, LAYERS * MLPD * DMODEL / 4);
    {
        int n4 = LAYERS * NHEAD * DHEAD * DHEAD / 4;
        cvt_kernel<<<(n4 + 255) / 256, 256>>>(Wq, p_wq, n4);
        cvt_kernel<<<(n4 + 255) / 256, 256>>>(Wk, p_wk, n4);
        cvt_kernel<<<(n4 + 255) / 256, 256>>>(Wv, p_wv, n4);
    }

    // 1) patchify + embed + assemble
    patchify_kernel<<<(NP * IN_DIM) / 256, 256>>>(images);
    {
        dim3 grid(DMODEL / 128, NP / 128);
        tgemm128<0><<<grid, 256, TG_SMEM>>>(p_patches, p_wmap, b_map, nullptr, p_mlp,
                                            NP, DMODEL, IN_DIM);
    }
    assemble_kernel<<<(NS * DMODEL) / 256, 256>>>(p_mlp, cls, pos);

    // 2) transformer blocks
    for (int l = 0; l < LAYERS; l++) {
        ln_kernel<<<NS, 256>>>(p_x, ln1_g + l * DMODEL, ln1_b + l * DMODEL, p_h);

        {
            dim3 grid((NS + 63) / 64, NHEAD, 3);
            qkv_kernel<<<grid, 128>>>(p_h,
                p_wq + (size_t)l * NHEAD * DHEAD * DHEAD,
                p_wk + (size_t)l * NHEAD * DHEAD * DHEAD,
                p_wv + (size_t)l * NHEAD * DHEAD * DHEAD,
                bq + (size_t)l * NHEAD * DHEAD,
                bk + (size_t)l * NHEAD * DHEAD,
                bv + (size_t)l * NHEAD * DHEAD,
                p_q, p_k, p_v);
        }
        {
            dim3 grid((SEQ + 63) / 64, NB * NHEAD);
            attn_kernel<<<grid, 128, ATTN_SMEM>>>(p_q, p_k, p_v, p_x);
        }

        ln_kernel<<<NS, 256>>>(p_x, ln2_g + l * DMODEL, ln2_b + l * DMODEL, p_h);
        {
            dim3 grid(MLPD / 128, (NS + 127) / 128);
            tgemm128<1><<<grid, 256, TG_SMEM>>>(p_h, p_w1 + (size_t)l * DMODEL * MLPD,
                                                b1 + (size_t)l * MLPD, nullptr, p_mlp,
                                                NS, MLPD, DMODEL);
        }
        {
            dim3 grid(DMODEL / 128, (NS + 127) / 128);
            tgemm128<2><<<grid, 256, TG_SMEM>>>(p_mlp, p_w2 + (size_t)l * MLPD * DMODEL,
                                                b2 + (size_t)l * DMODEL, p_x, p_x,
                                                NS, DMODEL, MLPD);
        }
    }

    // 3) head + softmax
    head_kernel<<<NB, 256>>>(p_x, W_head, b_head, out);
}

// round 8
// speedup vs baseline: 2.3782x; 1.0252x over previous
#include <cuda_runtime.h>
#include <cuda_bf16.h>
#include <math.h>
#include <cstdint>

// ---------------- problem constants ----------------
#define NB     32
#define SEQ    197
#define DMODEL 768
#define NHEAD  12
#define DHEAD  64
#define LAYERS 12
#define MLPD   3072
#define OUTD   1000
#define PPATCH 196
#define IN_DIM 768
#define NS     (NB * SEQ)       // 6304 tokens
#define NP     (NB * PPATCH)    // 6272 patches

// ---------------- device scratch ----------------
__device__ float g_patches[NP * IN_DIM];
__device__ float g_x[NS * DMODEL];
__device__ float g_h[NS * DMODEL];
__device__ float g_q[NS * DMODEL];
__device__ float g_k[NS * DMODEL];
__device__ float g_v[NS * DMODEL];
__device__ float g_mlp[NS * MLPD];
// pre-rounded (tf32 RNA) weight copies
__device__ float g_wmap[IN_DIM * DMODEL];
__device__ float g_w1[LAYERS * DMODEL * MLPD];
__device__ float g_w2[LAYERS * MLPD * DMODEL];
__device__ float g_wq[LAYERS * NHEAD * DHEAD * DHEAD];
__device__ float g_wk[LAYERS * NHEAD * DHEAD * DHEAD];
__device__ float g_wv[LAYERS * NHEAD * DHEAD * DHEAD];

__device__ __forceinline__ float tf32r(float x)
{
    float r;
    asm("cvt.rna.tf32.f32 %0, %1;" : "=f"(r) : "f"(x));
    return r;
}

__device__ __forceinline__ void mma_tf32(float* c, uint32_t a0, uint32_t a1,
                                         uint32_t a2, uint32_t a3,
                                         uint32_t b0, uint32_t b1)
{
    asm volatile(
        "mma.sync.aligned.m16n8k8.row.col.f32.tf32.tf32.f32 "
        "{%0,%1,%2,%3},{%4,%5,%6,%7},{%8,%9},{%0,%1,%2,%3};"
        : "+f"(c[0]), "+f"(c[1]), "+f"(c[2]), "+f"(c[3])
        : "r"(a0), "r"(a1), "r"(a2), "r"(a3), "r"(b0), "r"(b1));
}

// ---------------- weight pre-rounding ----------------
__global__ void __launch_bounds__(256)
cvt_kernel(const float* __restrict__ src, float* __restrict__ dst, int n4)
{
    int i = blockIdx.x * 256 + threadIdx.x;
    if (i >= n4) return;
    float4 v = ((const float4*)src)[i];
    v.x = tf32r(v.x); v.y = tf32r(v.y); v.z = tf32r(v.z); v.w = tf32r(v.w);
    ((float4*)dst)[i] = v;
}

// ---------------- patchify (pre-rounded: feeds GEMM A) ----------------
__global__ void __launch_bounds__(256)
patchify_kernel(const float* __restrict__ img)
{
    int idx = blockIdx.x * 256 + threadIdx.x;
    if (idx >= NP * IN_DIM) return;
    int t = idx / IN_DIM;
    int e = idx - t * IN_DIM;
    int n = t / PPATCH;
    int p = t - n * PPATCH;
    int py = p / 14, px = p - py * 14;
    int c  = e >> 8;
    int r  = e & 255;
    int ph = r >> 4, pw = r & 15;
    g_patches[idx] = tf32r(img[(((size_t)n * 3 + c) * 224 + (py * 16 + ph)) * 224 + px * 16 + pw]);
}

// ---------------- assemble ----------------
__global__ void __launch_bounds__(256)
assemble_kernel(const float* __restrict__ tokens, const float* __restrict__ cls,
                const float* __restrict__ pos)
{
    int idx = blockIdx.x * 256 + threadIdx.x;
    if (idx >= NS * DMODEL) return;
    int t = idx / DMODEL;
    int d = idx - t * DMODEL;
    int n = t / SEQ;
    int s = t - n * SEQ;
    float v = (s == 0) ? cls[d] : tokens[((size_t)(n * PPATCH + s - 1)) * DMODEL + d];
    g_x[idx] = v + pos[s * DMODEL + d];
}

// ---------------- 3-stage pipelined tf32 GEMM (cvt-free) ----------------
// One __syncthreads per K-tile; loads run two tiles ahead.
#define TG_STAGE_F (128 * 36 + 32 * 132)               // floats per stage
#define TG_SMEM    (3 * TG_STAGE_F * 4)                 // 105984 bytes

template<int EPI>
__global__ void __launch_bounds__(256, 2)
tgemm128(const float* __restrict__ A, const float* __restrict__ B,
         const float* __restrict__ bias, const float* __restrict__ res,
         float* __restrict__ C, int M, int N, int K)
{
    extern __shared__ float smem[];

    const int tid  = threadIdx.x;
    const int wid  = tid >> 5;
    const int lane = tid & 31;
    const int g    = lane >> 2;
    const int tig  = lane & 3;
    const int mw   = wid & 3;
    const int nw   = wid >> 2;
    const int bm   = blockIdx.y * 128;
    const int bn   = blockIdx.x * 128;

    float acc[2][8][4];
    #pragma unroll
    for (int i = 0; i < 2; i++)
        #pragma unroll
        for (int j = 0; j < 8; j++)
            #pragma unroll
            for (int c = 0; c < 4; c++) acc[i][j][c] = 0.f;

    auto As = [&](int buf) {
        return reinterpret_cast<float(*)[36]>(smem + buf * TG_STAGE_F);
    };
    auto Bs = [&](int buf) {
        return reinterpret_cast<float(*)[132]>(smem + buf * TG_STAGE_F + 128 * 36);
    };

    auto load_tiles = [&](int kk0, int buf) {
        float (*as)[36]  = As(buf);
        float (*bs)[132] = Bs(buf);
        #pragma unroll
        for (int p = 0; p < 4; p++) {
            int idx = p * 256 + tid;
            int m   = idx >> 3;
            int c4  = (idx & 7) * 4;
            const float* src = A + (size_t)(bm + m) * K + kk0 + c4;
            uint32_t dst = (uint32_t)__cvta_generic_to_shared(&as[m][c4]);
            int sz = (bm + m) < M ? 16 : 0;
            asm volatile("cp.async.cg.shared.global [%0], [%1], 16, %2;"
                         :: "r"(dst), "l"(src), "r"(sz) : "memory");
        }
        #pragma unroll
        for (int p = 0; p < 4; p++) {
            int idx = p * 256 + tid;
            int kr  = idx >> 5;
            int n4  = (idx & 31) * 4;
            const float* src = B + (size_t)(kk0 + kr) * N + bn + n4;
            uint32_t dst = (uint32_t)__cvta_generic_to_shared(&bs[kr][n4]);
            asm volatile("cp.async.cg.shared.global [%0], [%1], 16;"
                         :: "r"(dst), "l"(src) : "memory");
        }
        asm volatile("cp.async.commit_group;" ::: "memory");
    };

    const int T = K >> 5;
    load_tiles(0, 0);
    if (T > 1) load_tiles(32, 1);

    int buf = 0;
    for (int kt = 0; kt < T; kt++) {
        if (kt + 1 < T) {
            asm volatile("cp.async.wait_group 1;" ::: "memory");
        } else {
            asm volatile("cp.async.wait_group 0;" ::: "memory");
        }
        __syncthreads();

        if (kt + 2 < T) load_tiles((kt + 2) << 5, (kt + 2) % 3);

        float (*as)[36]  = As(buf);
        float (*bs)[132] = Bs(buf);

        #pragma unroll
        for (int ks = 0; ks < 4; ks++) {
            const int kk = ks * 8;
            uint32_t af[2][4];
            #pragma unroll
            for (int mt = 0; mt < 2; mt++) {
                int rb = mw * 32 + mt * 16;
                af[mt][0] = __float_as_uint(as[rb + g]    [kk + tig]);
                af[mt][1] = __float_as_uint(as[rb + g + 8][kk + tig]);
                af[mt][2] = __float_as_uint(as[rb + g]    [kk + tig + 4]);
                af[mt][3] = __float_as_uint(as[rb + g + 8][kk + tig + 4]);
            }
            uint32_t bf[8][2];
            #pragma unroll
            for (int nt = 0; nt < 8; nt++) {
                int cb = nw * 64 + nt * 8 + g;
                bf[nt][0] = __float_as_uint(bs[kk + tig]    [cb]);
                bf[nt][1] = __float_as_uint(bs[kk + tig + 4][cb]);
            }
            #pragma unroll
            for (int mt = 0; mt < 2; mt++)
                #pragma unroll
                for (int nt = 0; nt < 8; nt++)
                    mma_tf32(acc[mt][nt], af[mt][0], af[mt][1], af[mt][2], af[mt][3],
                             bf[nt][0], bf[nt][1]);
        }
        buf = (buf == 2) ? 0 : buf + 1;
    }

    #pragma unroll
    for (int mt = 0; mt < 2; mt++) {
        int r0 = bm + mw * 32 + mt * 16 + g;
        int r1 = r0 + 8;
        #pragma unroll
        for (int nt = 0; nt < 8; nt++) {
            int c0 = bn + nw * 64 + nt * 8 + 2 * tig;
            float b0 = bias[c0], b1 = bias[c0 + 1];
            #pragma unroll
            for (int half = 0; half < 2; half++) {
                int row = half ? r1 : r0;
                if (row >= M) continue;
                float v0 = acc[mt][nt][half * 2 + 0] + b0;
                float v1 = acc[mt][nt][half * 2 + 1] + b1;
                if (EPI == 1) {
                    v0 = tf32r(0.5f * v0 * (1.f + erff(v0 * 0.70710678118654752f)));
                    v1 = tf32r(0.5f * v1 * (1.f + erff(v1 * 0.70710678118654752f)));
                }
                if (EPI == 2) {
                    const float2 rr = *(const float2*)(res + (size_t)row * N + c0);
                    v0 += rr.x; v1 += rr.y;
                }
                float2 o; o.x = v0; o.y = v1;
                *(float2*)(C + (size_t)row * N + c0) = o;
            }
        }
    }
}

// ---------------- LayerNorm (output pre-rounded) ----------------
__global__ void __launch_bounds__(256)
ln_kernel(const float* __restrict__ x, const float* __restrict__ g,
          const float* __restrict__ b, float* __restrict__ o)
{
    int row = blockIdx.x;
    int tid = threadIdx.x;
    const float* xr = x + (size_t)row * DMODEL;
    float v0 = xr[tid], v1 = xr[tid + 256], v2 = xr[tid + 512];

    __shared__ float red[10];
    float s = v0 + v1 + v2;
    #pragma unroll
    for (int of = 16; of; of >>= 1) s += __shfl_xor_sync(~0u, s, of);
    if ((tid & 31) == 0) red[tid >> 5] = s;
    __syncthreads();
    if (tid == 0) {
        float t = 0.f;
        #pragma unroll
        for (int i = 0; i < 8; i++) t += red[i];
        red[8] = t * (1.f / 768.f);
    }
    __syncthreads();
    float mu = red[8];
    float d0 = v0 - mu, d1 = v1 - mu, d2 = v2 - mu;
    float q = d0 * d0 + d1 * d1 + d2 * d2;
    #pragma unroll
    for (int of = 16; of; of >>= 1) q += __shfl_xor_sync(~0u, q, of);
    if ((tid & 31) == 0) red[tid >> 5] = q;
    __syncthreads();
    if (tid == 0) {
        float t = 0.f;
        #pragma unroll
        for (int i = 0; i < 8; i++) t += red[i];
        red[9] = rsqrtf(t * (1.f / 768.f) + 1e-5f);
    }
    __syncthreads();
    float inv = red[9];
    float* orow = o + (size_t)row * DMODEL;
    orow[tid]       = tf32r(d0 * inv * g[tid]       + b[tid]);
    orow[tid + 256] = tf32r(d1 * inv * g[tid + 256] + b[tid + 256]);
    orow[tid + 512] = tf32r(d2 * inv * g[tid + 512] + b[tid + 512]);
}

// ---------------- per-head QKV projection, tf32 mma ----------------
__global__ void __launch_bounds__(128)
qkv_kernel(const float* __restrict__ h,
           const float* __restrict__ Wq, const float* __restrict__ Wk, const float* __restrict__ Wv,
           const float* __restrict__ bq, const float* __restrict__ bk, const float* __restrict__ bv,
           float* __restrict__ q, float* __restrict__ k, float* __restrict__ v)
{
    __shared__ float Xs[64][68];   // [token][d]
    __shared__ float Ws[64][68];   // [d][e]

    const int t0 = blockIdx.x * 64;
    const int hh = blockIdx.y;
    const int z  = blockIdx.z;
    const float* W  = ((z == 0) ? Wq : (z == 1) ? Wk : Wv) + hh * 64 * 64;
    const float* bb = ((z == 0) ? bq : (z == 1) ? bk : bv) + hh * 64;
    float* out      = (z == 0) ? q  : (z == 1) ? k  : v;

    const int tid  = threadIdx.x;
    const int wid  = tid >> 5;
    const int lane = tid & 31;
    const int g    = lane >> 2;
    const int tig  = lane & 3;
    const int rb   = wid * 16;

    #pragma unroll
    for (int it = 0; it < 8; it++) {
        int idx = it * 128 + tid;
        int row = idx >> 4;
        int col = (idx & 15) * 4;
        int tok = t0 + row;
        float4 xv = make_float4(0.f, 0.f, 0.f, 0.f);
        if (tok < NS) xv = *(const float4*)(h + (size_t)tok * DMODEL + hh * 64 + col);
        *(float4*)&Xs[row][col] = xv;
        *(float4*)&Ws[row][col] = *(const float4*)(W + row * 64 + col);
    }
    __syncthreads();

    float acc[8][4];
    #pragma unroll
    for (int nt = 0; nt < 8; nt++)
        #pragma unroll
        for (int c = 0; c < 4; c++) acc[nt][c] = 0.f;

    #pragma unroll
    for (int ks = 0; ks < 8; ks++) {
        const int kk = ks * 8;
        uint32_t a0 = __float_as_uint(Xs[rb + g]    [kk + tig]);
        uint32_t a1 = __float_as_uint(Xs[rb + g + 8][kk + tig]);
        uint32_t a2 = __float_as_uint(Xs[rb + g]    [kk + tig + 4]);
        uint32_t a3 = __float_as_uint(Xs[rb + g + 8][kk + tig + 4]);
        #pragma unroll
        for (int nt = 0; nt < 8; nt++) {
            uint32_t b0 = __float_as_uint(Ws[kk + tig]    [nt * 8 + g]);
            uint32_t b1 = __float_as_uint(Ws[kk + tig + 4][nt * 8 + g]);
            mma_tf32(acc[nt], a0, a1, a2, a3, b0, b1);
        }
    }

    #pragma unroll
    for (int nt = 0; nt < 8; nt++) {
        int col = nt * 8 + 2 * tig;
        float b0 = bb[col], b1 = bb[col + 1];
        #pragma unroll
        for (int half = 0; half < 2; half++) {
            int tok = t0 + rb + g + half * 8;
            if (tok >= NS) continue;
            float2 o;
            o.x = tf32r(acc[nt][half * 2 + 0] + b0);
            o.y = tf32r(acc[nt][half * 2 + 1] + b1);
            *(float2*)(out + (size_t)tok * DMODEL + hh * 64 + col) = o;
        }
    }
}

// ---------------- fused flash attention, tf32 mma ----------------
#define ATTN_SMEM ((3 * 64 * 68 + 64 * 72) * 4)   // 70656 bytes

__global__ void __launch_bounds__(128)
attn_kernel(const float* __restrict__ q, const float* __restrict__ k,
            const float* __restrict__ v, float* __restrict__ x)
{
    extern __shared__ float sm[];
    float (*Qs)[68] = reinterpret_cast<float(*)[68]>(sm);                 // [q][d]
    float (*Ks)[68] = reinterpret_cast<float(*)[68]>(sm + 64 * 68);      // [key][d]
    float (*Ps)[68] = reinterpret_cast<float(*)[68]>(sm + 2 * 64 * 68);  // [q][key]
    float (*Vs)[72] = reinterpret_cast<float(*)[72]>(sm + 3 * 64 * 68);  // [key][e]

    const int q0 = blockIdx.x * 64;
    const int b  = blockIdx.y;
    const int n  = b / NHEAD, hh = b - n * NHEAD;
    const int tid  = threadIdx.x;
    const int wid  = tid >> 5;
    const int lane = tid & 31;
    const int g    = lane >> 2;
    const int tig  = lane & 3;
    const int rb   = wid * 16;

    #pragma unroll
    for (int it = 0; it < 8; it++) {
        int idx = it * 128 + tid;
        int row = idx >> 4;
        int col = (idx & 15) * 4;
        int qt = q0 + row;
        float4 qv = make_float4(0.f, 0.f, 0.f, 0.f);
        if (qt < SEQ) qv = *(const float4*)(q + (size_t)(n * SEQ + qt) * DMODEL + hh * 64 + col);
        *(float4*)&Qs[row][col] = qv;
    }

    float m_run[2] = {-1e30f, -1e30f};
    float l_run[2] = {0.f, 0.f};
    float acc_o[8][4];
    #pragma unroll
    for (int nt = 0; nt < 8; nt++)
        #pragma unroll
        for (int c = 0; c < 4; c++) acc_o[nt][c] = 0.f;

    for (int kt = 0; kt < 4; kt++) {
        const int k0 = kt * 64;
        __syncthreads();

        #pragma unroll
        for (int it = 0; it < 8; it++) {
            int idx = it * 128 + tid;
            int row = idx >> 4;
            int col = (idx & 15) * 4;
            int ktok = k0 + row;
            float4 kv = make_float4(0.f, 0.f, 0.f, 0.f);
            float4 vv = make_float4(0.f, 0.f, 0.f, 0.f);
            if (ktok < SEQ) {
                kv = *(const float4*)(k + (size_t)(n * SEQ + ktok) * DMODEL + hh * 64 + col);
                vv = *(const float4*)(v + (size_t)(n * SEQ + ktok) * DMODEL + hh * 64 + col);
            }
            *(float4*)&Ks[row][col] = kv;
            *(float4*)&Vs[row][col] = vv;
        }
        __syncthreads();

        float s[8][4];
        #pragma unroll
        for (int nt = 0; nt < 8; nt++)
            #pragma unroll
            for (int c = 0; c < 4; c++) s[nt][c] = 0.f;

        #pragma unroll
        for (int ks = 0; ks < 8; ks++) {
            const int kk = ks * 8;
            uint32_t a0 = __float_as_uint(Qs[rb + g]    [kk + tig]);
            uint32_t a1 = __float_as_uint(Qs[rb + g + 8][kk + tig]);
            uint32_t a2 = __float_as_uint(Qs[rb + g]    [kk + tig + 4]);
            uint32_t a3 = __float_as_uint(Qs[rb + g + 8][kk + tig + 4]);
            #pragma unroll
            for (int nt = 0; nt < 8; nt++) {
                uint32_t b0 = __float_as_uint(Ks[nt * 8 + g][kk + tig]);
                uint32_t b1 = __float_as_uint(Ks[nt * 8 + g][kk + tig + 4]);
                mma_tf32(s[nt], a0, a1, a2, a3, b0, b1);
            }
        }

        #pragma unroll
        for (int nt = 0; nt < 8; nt++) {
            int c0 = k0 + nt * 8 + 2 * tig;
            s[nt][0] = (c0     < SEQ) ? s[nt][0] * 0.125f : -1e30f;
            s[nt][1] = (c0 + 1 < SEQ) ? s[nt][1] * 0.125f : -1e30f;
            s[nt][2] = (c0     < SEQ) ? s[nt][2] * 0.125f : -1e30f;
            s[nt][3] = (c0 + 1 < SEQ) ? s[nt][3] * 0.125f : -1e30f;
        }

        #pragma unroll
        for (int r = 0; r < 2; r++) {
            float mt_ = -1e30f;
            #pragma unroll
            for (int nt = 0; nt < 8; nt++)
                mt_ = fmaxf(mt_, fmaxf(s[nt][2 * r], s[nt][2 * r + 1]));
            mt_ = fmaxf(mt_, __shfl_xor_sync(~0u, mt_, 1));
            mt_ = fmaxf(mt_, __shfl_xor_sync(~0u, mt_, 2));
            float mnew = fmaxf(m_run[r], mt_);
            float sc = expf(m_run[r] - mnew);
            float rs = 0.f;
            #pragma unroll
            for (int nt = 0; nt < 8; nt++) {
                float p0 = expf(s[nt][2 * r]     - mnew);
                float p1 = expf(s[nt][2 * r + 1] - mnew);
                s[nt][2 * r] = p0; s[nt][2 * r + 1] = p1;
                rs += p0 + p1;
            }
            rs += __shfl_xor_sync(~0u, rs, 1);
            rs += __shfl_xor_sync(~0u, rs, 2);
            l_run[r] = l_run[r] * sc + rs;
            #pragma unroll
            for (int nt = 0; nt < 8; nt++) {
                acc_o[nt][2 * r]     *= sc;
                acc_o[nt][2 * r + 1] *= sc;
            }
            m_run[r] = mnew;
        }

        #pragma unroll
        for (int nt = 0; nt < 8; nt++) {
            float2 p0; p0.x = tf32r(s[nt][0]); p0.y = tf32r(s[nt][1]);
            float2 p1; p1.x = tf32r(s[nt][2]); p1.y = tf32r(s[nt][3]);
            *(float2*)&Ps[rb + g]    [nt * 8 + 2 * tig] = p0;
            *(float2*)&Ps[rb + g + 8][nt * 8 + 2 * tig] = p1;
        }
        __syncwarp();

        #pragma unroll
        for (int ks = 0; ks < 8; ks++) {
            const int kk = ks * 8;
            uint32_t a0 = __float_as_uint(Ps[rb + g]    [kk + tig]);
            uint32_t a1 = __float_as_uint(Ps[rb + g + 8][kk + tig]);
            uint32_t a2 = __float_as_uint(Ps[rb + g]    [kk + tig + 4]);
            uint32_t a3 = __float_as_uint(Ps[rb + g + 8][kk + tig + 4]);
            #pragma unroll
            for (int nt = 0; nt < 8; nt++) {
                uint32_t b0 = __float_as_uint(Vs[kk + tig]    [nt * 8 + g]);
                uint32_t b1 = __float_as_uint(Vs[kk + tig + 4][nt * 8 + g]);
                mma_tf32(acc_o[nt], a0, a1, a2, a3, b0, b1);
            }
        }
    }

    #pragma unroll
    for (int r = 0; r < 2; r++) {
        int row = q0 + rb + g + r * 8;
        if (row >= SEQ) continue;
        float inv = 1.f / l_run[r];
        #pragma unroll
        for (int nt = 0; nt < 8; nt++) {
            int col = hh * 64 + nt * 8 + 2 * tig;
            float* px = x + (size_t)(n * SEQ + row) * DMODEL + col;
            float2 old = *(float2*)px;
            old.x += acc_o[nt][2 * r]     * inv;
            old.y += acc_o[nt][2 * r + 1] * inv;
            *(float2*)px = old;
        }
    }
}

// ---------------- head + softmax ----------------
__global__ void __launch_bounds__(256)
head_kernel(const float* __restrict__ x, const float* __restrict__ Wh,
            const float* __restrict__ bh, float* __restrict__ out)
{
    __shared__ float xs[DMODEL];
    __shared__ float lg[OUTD];
    __shared__ float red[256];
    int n = blockIdx.x, tid = threadIdx.x;
    for (int i = tid; i < DMODEL; i += 256) xs[i] = x[(size_t)n * SEQ * DMODEL + i];
    __syncthreads();
    for (int o = tid; o < OUTD; o += 256) {
        float a = bh[o];
        for (int kk = 0; kk < DMODEL; kk++)
            a = fmaf(xs[kk], Wh[(size_t)kk * OUTD + o], a);
        lg[o] = a;
    }
    __syncthreads();
    float m = -1e30f;
    for (int o = tid; o < OUTD; o += 256) m = fmaxf(m, lg[o]);
    red[tid] = m; __syncthreads();
    for (int s = 128; s; s >>= 1) { if (tid < s) red[tid] = fmaxf(red[tid], red[tid + s]); __syncthreads(); }
    float mx = red[0]; __syncthreads();
    float sm = 0.f;
    for (int o = tid; o < OUTD; o += 256) sm += expf(lg[o] - mx);
    red[tid] = sm; __syncthreads();
    for (int s = 128; s; s >>= 1) { if (tid < s) red[tid] += red[tid + s]; __syncthreads(); }
    float inv = 1.f / red[0];
    __syncthreads();
    for (int o = tid; o < OUTD; o += 256)
        out[(size_t)n * OUTD + o] = expf(lg[o] - mx) * inv;
}

// ---------------- host orchestration ----------------
extern "C" void kernel_launch(void* const* d_in, const int* in_sizes, int n_in,
                              void* d_out, int out_size)
{
    const float* images   = (const float*)d_in[0];
    const float* W_map    = (const float*)d_in[1];
    const float* b_map    = (const float*)d_in[2];
    const float* cls      = (const float*)d_in[3];
    const float* pos      = (const float*)d_in[4];
    const float* ln1_g    = (const float*)d_in[5];
    const float* ln1_b    = (const float*)d_in[6];
    const float* Wq       = (const float*)d_in[7];
    const float* bq       = (const float*)d_in[8];
    const float* Wk       = (const float*)d_in[9];
    const float* bk       = (const float*)d_in[10];
    const float* Wv       = (const float*)d_in[11];
    const float* bv       = (const float*)d_in[12];
    const float* ln2_g    = (const float*)d_in[13];
    const float* ln2_b    = (const float*)d_in[14];
    const float* W1       = (const float*)d_in[15];
    const float* b1       = (const float*)d_in[16];
    const float* W2       = (const float*)d_in[17];
    const float* b2       = (const float*)d_in[18];
    const float* W_head   = (const float*)d_in[19];
    const float* b_head   = (const float*)d_in[20];
    float* out = (float*)d_out;

    float *p_patches, *p_x, *p_h, *p_q, *p_k, *p_v, *p_mlp;
    float *p_wmap, *p_w1, *p_w2, *p_wq, *p_wk, *p_wv;
    cudaGetSymbolAddress((void**)&p_patches, g_patches);
    cudaGetSymbolAddress((void**)&p_x, g_x);
    cudaGetSymbolAddress((void**)&p_h, g_h);
    cudaGetSymbolAddress((void**)&p_q, g_q);
    cudaGetSymbolAddress((void**)&p_k, g_k);
    cudaGetSymbolAddress((void**)&p_v, g_v);
    cudaGetSymbolAddress((void**)&p_mlp, g_mlp);
    cudaGetSymbolAddress((void**)&p_wmap, g_wmap);
    cudaGetSymbolAddress((void**)&p_w1, g_w1);
    cudaGetSymbolAddress((void**)&p_w2, g_w2);
    cudaGetSymbolAddress((void**)&p_wq, g_wq);
    cudaGetSymbolAddress((void**)&p_wk, g_wk);
    cudaGetSymbolAddress((void**)&p_wv, g_wv);

    cudaFuncSetAttribute(tgemm128<0>, cudaFuncAttributeMaxDynamicSharedMemorySize, TG_SMEM);
    cudaFuncSetAttribute(tgemm128<1>, cudaFuncAttributeMaxDynamicSharedMemorySize, TG_SMEM);
    cudaFuncSetAttribute(tgemm128<2>, cudaFuncAttributeMaxDynamicSharedMemorySize, TG_SMEM);
    cudaFuncSetAttribute(attn_kernel, cudaFuncAttributeMaxDynamicSharedMemorySize, ATTN_SMEM);

    // 0) pre-round weights to tf32 (RNA)
    cvt_kernel<<<(IN_DIM * DMODEL / 4 + 255) / 256, 256>>>(W_map, p_wmap, IN_DIM * DMODEL / 4);
    cvt_kernel<<<(LAYERS * DMODEL * MLPD / 4 + 255) / 256, 256>>>(W1, p_w1, LAYERS * DMODEL * MLPD / 4);
    cvt_kernel<<<(LAYERS * MLPD * DMODEL / 4 + 255) / 256, 256>>>(W2, p_w2, LAYERS * MLPD * DMODEL / 4);
    {
        int n4 = LAYERS * NHEAD * DHEAD * DHEAD / 4;
        cvt_kernel<<<(n4 + 255) / 256, 256>>>(Wq, p_wq, n4);
        cvt_kernel<<<(n4 + 255) / 256, 256>>>(Wk, p_wk, n4);
        cvt_kernel<<<(n4 + 255) / 256, 256>>>(Wv, p_wv, n4);
    }

    // 1) patchify + embed + assemble
    patchify_kernel<<<(NP * IN_DIM) / 256, 256>>>(images);
    {
        dim3 grid(DMODEL / 128, NP / 128);
        tgemm128<0><<<grid, 256, TG_SMEM>>>(p_patches, p_wmap, b_map, nullptr, p_mlp,
                                            NP, DMODEL, IN_DIM);
    }
    assemble_kernel<<<(NS * DMODEL) / 256, 256>>>(p_mlp, cls, pos);

    // 2) transformer blocks
    for (int l = 0; l < LAYERS; l++) {
        ln_kernel<<<NS, 256>>>(p_x, ln1_g + l * DMODEL, ln1_b + l * DMODEL, p_h);

        {
            dim3 grid((NS + 63) / 64, NHEAD, 3);
            qkv_kernel<<<grid, 128>>>(p_h,
                p_wq + (size_t)l * NHEAD * DHEAD * DHEAD,
                p_wk + (size_t)l * NHEAD * DHEAD * DHEAD,
                p_wv + (size_t)l * NHEAD * DHEAD * DHEAD,
                bq + (size_t)l * NHEAD * DHEAD,
                bk + (size_t)l * NHEAD * DHEAD,
                bv + (size_t)l * NHEAD * DHEAD,
                p_q, p_k, p_v);
        }
        {
            dim3 grid((SEQ + 63) / 64, NB * NHEAD);
            attn_kernel<<<grid, 128, ATTN_SMEM>>>(p_q, p_k, p_v, p_x);
        }

        ln_kernel<<<NS, 256>>>(p_x, ln2_g + l * DMODEL, ln2_b + l * DMODEL, p_h);
        {
            dim3 grid(MLPD / 128, (NS + 127) / 128);
            tgemm128<1><<<grid, 256, TG_SMEM>>>(p_h, p_w1 + (size_t)l * DMODEL * MLPD,
                                                b1 + (size_t)l * MLPD, nullptr, p_mlp,
                                                NS, MLPD, DMODEL);
        }
        {
            dim3 grid(DMODEL / 128, (NS + 127) / 128);
            tgemm128<2><<<grid, 256, TG_SMEM>>>(p_mlp, p_w2 + (size_t)l * MLPD * DMODEL,
                                                b2 + (size_t)l * DMODEL, p_x, p_x,
                                                NS, DMODEL, MLPD);
        }
    }

    // 3) head + softmax
    head_kernel<<<NB, 256>>>(p_x, W_head, b_head, out);
}

// round 10
// speedup vs baseline: 3.4722x; 1.4600x over previous
#include <cuda_runtime.h>
#include <cuda_bf16.h>
#include <cuda_fp16.h>
#include <math.h>
#include <cstdint>

// ---------------- problem constants ----------------
#define NB     32
#define SEQ    197
#define DMODEL 768
#define NHEAD  12
#define DHEAD  64
#define LAYERS 12
#define MLPD   3072
#define OUTD   1000
#define PPATCH 196
#define IN_DIM 768
#define NS     (NB * SEQ)       // 6304 tokens
#define NP     (NB * PPATCH)    // 6272 patches

// ---------------- device scratch ----------------
__device__ __half g_patches16[NP * IN_DIM];        // embed A (fp16, k-interleaved)
__device__ float  g_tokens[NP * DMODEL];           // embed output (fp32)
__device__ float  g_x[NS * DMODEL];                // residual stream (fp32)
__device__ float  g_hf[NS * DMODEL];               // ln1 out (fp32, attention path)
__device__ __half g_h16[NS * DMODEL];              // ln2 out (fp16, interleaved, MLP A)
__device__ float  g_q[NS * DMODEL];
__device__ float  g_k[NS * DMODEL];
__device__ float  g_v[NS * DMODEL];
__device__ __half g_mlp16[NS * MLPD];              // MLP1 out (fp16, interleaved)
// weights
__device__ __half g_wmapT16[DMODEL * IN_DIM];      // [N][K] fp16, K interleaved
__device__ __half g_w1T16[LAYERS * MLPD * DMODEL];
__device__ __half g_w2T16[LAYERS * DMODEL * MLPD];
__device__ float  g_wq[LAYERS * NHEAD * DHEAD * DHEAD];  // tf32-rounded (attention path)
__device__ float  g_wk[LAYERS * NHEAD * DHEAD * DHEAD];
__device__ float  g_wv[LAYERS * NHEAD * DHEAD * DHEAD];

__device__ __forceinline__ float tf32r(float x)
{
    float r;
    asm("cvt.rna.tf32.f32 %0, %1;" : "=f"(r) : "f"(x));
    return r;
}

// k-interleave within 16-groups: perm = [0,1,4,5,8,9,12,13,2,3,6,7,10,11,14,15]
__device__ __forceinline__ int il16(int c)
{
    int r = c & 15;
    int p = ((r & 7) >> 1) * 4 + ((r >> 3) << 1) + (r & 1);
    return (c & ~15) | p;
}
__device__ __forceinline__ int inv16(int c)   // inverse permutation
{
    int r = c & 15;
    int k = (((r & 3) < 2) ? 0 : 8) + ((r >> 2) << 1) + (r & 1);
    return (c & ~15) | k;
}

__device__ __forceinline__ void mma_tf32(float* c, uint32_t a0, uint32_t a1,
                                         uint32_t a2, uint32_t a3,
                                         uint32_t b0, uint32_t b1)
{
    asm volatile(
        "mma.sync.aligned.m16n8k8.row.col.f32.tf32.tf32.f32 "
        "{%0,%1,%2,%3},{%4,%5,%6,%7},{%8,%9},{%0,%1,%2,%3};"
        : "+f"(c[0]), "+f"(c[1]), "+f"(c[2]), "+f"(c[3])
        : "r"(a0), "r"(a1), "r"(a2), "r"(a3), "r"(b0), "r"(b1));
}

__device__ __forceinline__ void mma_f16(float* c, uint32_t a0, uint32_t a1,
                                        uint32_t a2, uint32_t a3,
                                        uint32_t b0, uint32_t b1)
{
    asm volatile(
        "mma.sync.aligned.m16n8k16.row.col.f32.f16.f16.f32 "
        "{%0,%1,%2,%3},{%4,%5,%6,%7},{%8,%9},{%0,%1,%2,%3};"
        : "+f"(c[0]), "+f"(c[1]), "+f"(c[2]), "+f"(c[3])
        : "r"(a0), "r"(a1), "r"(a2), "r"(a3), "r"(b0), "r"(b1));
}

// ---------------- weight prep ----------------
// qkv weights: fp32 tf32-round (attention path unchanged)
__global__ void __launch_bounds__(256)
cvt_kernel(const float* __restrict__ src, float* __restrict__ dst, int n4)
{
    int i = blockIdx.x * 256 + threadIdx.x;
    if (i >= n4) return;
    float4 v = ((const float4*)src)[i];
    v.x = tf32r(v.x); v.y = tf32r(v.y); v.z = tf32r(v.z); v.w = tf32r(v.w);
    ((float4*)dst)[i] = v;
}

// big GEMM weights: fp16 + transpose src[R][C] -> dst[C][R], R(=K) interleaved
__global__ void __launch_bounds__(256)
cvtT16_kernel(const float* __restrict__ src, __half* __restrict__ dst, int R, int C)
{
    __shared__ float t[32][33];
    size_t zoff = (size_t)blockIdx.z * R * C;
    int bx = blockIdx.x * 32;
    int by = blockIdx.y * 32;
    int tx = threadIdx.x & 31;
    int ty = threadIdx.x >> 5;
    #pragma unroll
    for (int i = 0; i < 32; i += 8)
        t[ty + i][tx] = src[zoff + (size_t)(by + ty + i) * C + bx + tx];
    __syncthreads();
    int kp = il16(by + tx);
    #pragma unroll
    for (int i = 0; i < 32; i += 8)
        dst[zoff + (size_t)(bx + ty + i) * R + kp] = __float2half(t[tx][ty + i]);
}

// ---------------- patchify (fp16, k-interleaved) ----------------
__global__ void __launch_bounds__(256)
patchify_kernel(const float* __restrict__ img)
{
    int idx = blockIdx.x * 256 + threadIdx.x;
    if (idx >= NP * IN_DIM) return;
    int t = idx / IN_DIM;
    int ep = idx - t * IN_DIM;
    int e = inv16(ep);           // source feature for this interleaved slot
    int n = t / PPATCH;
    int p = t - n * PPATCH;
    int py = p / 14, px = p - py * 14;
    int c  = e >> 8;
    int r  = e & 255;
    int ph = r >> 4, pw = r & 15;
    g_patches16[idx] = __float2half(
        img[(((size_t)n * 3 + c) * 224 + (py * 16 + ph)) * 224 + px * 16 + pw]);
}

// ---------------- assemble ----------------
__global__ void __launch_bounds__(256)
assemble_kernel(const float* __restrict__ tokens, const float* __restrict__ cls,
                const float* __restrict__ pos)
{
    int idx = blockIdx.x * 256 + threadIdx.x;
    if (idx >= NS * DMODEL) return;
    int t = idx / DMODEL;
    int d = idx - t * DMODEL;
    int n = t / SEQ;
    int s = t - n * SEQ;
    float v = (s == 0) ? cls[d] : tokens[((size_t)(n * PPATCH + s - 1)) * DMODEL + d];
    g_x[idx] = v + pos[s * DMODEL + d];
}

// ---------------- fp16 tensor-core GEMM: C = A @ Bt^T + bias (+epilogue) ----------
// A [M][K] fp16 k-interleaved; Bt [N][K] fp16 k-interleaved. Tile 128x128, BK=32.
// 128 threads (4 warps, 2x2), warp tile 64x64. 3-stage cp.async, 1 barrier/tile.
// Smem rows stride 48 halves (96B) -> conflict-free LDS.64 fragments.
// EPI: 0 = bias -> fp32 out; 1 = bias+GELU -> fp16 out (N-interleaved); 2 = bias+residual -> fp32.
#define TG16_STAGE 24576
#define TG16_SMEM  (3 * TG16_STAGE)   // 73728 bytes

template<int EPI>
__global__ void __launch_bounds__(128, 2)
tgemm16(const __half* __restrict__ A, const __half* __restrict__ Bt,
        const float* __restrict__ bias, const float* __restrict__ res,
        void* __restrict__ Cv, int M, int N, int K)
{
    extern __shared__ char sm16[];

    const int tid  = threadIdx.x;
    const int wid  = tid >> 5;
    const int lane = tid & 31;
    const int g    = lane >> 2;
    const int tig  = lane & 3;
    const int mw   = wid & 1;
    const int nw   = wid >> 1;
    const int bm   = blockIdx.y * 128;
    const int bn   = blockIdx.x * 128;

    float acc[4][8][4];
    #pragma unroll
    for (int i = 0; i < 4; i++)
        #pragma unroll
        for (int j = 0; j < 8; j++)
            #pragma unroll
            for (int c = 0; c < 4; c++) acc[i][j][c] = 0.f;

    auto As = [&](int buf) { return (__half*)(sm16 + buf * TG16_STAGE); };
    auto Bs = [&](int buf) { return (__half*)(sm16 + buf * TG16_STAGE + 12288); };

    auto load_tile = [&](int kt, int buf) {
        __half* as = As(buf);
        __half* bs = Bs(buf);
        const int kk0 = kt * 32;
        #pragma unroll
        for (int p = 0; p < 4; p++) {
            int idx = p * 128 + tid;
            int row = idx >> 2;
            int ch  = idx & 3;            // 16B = 8 halves
            const __half* src = A + (size_t)(bm + row) * K + kk0 + ch * 8;
            uint32_t dst = (uint32_t)__cvta_generic_to_shared(as + row * 48 + ch * 8);
            int sz = (bm + row) < M ? 16 : 0;
            asm volatile("cp.async.cg.shared.global [%0], [%1], 16, %2;"
                         :: "r"(dst), "l"(src), "r"(sz) : "memory");
        }
        #pragma unroll
        for (int p = 0; p < 4; p++) {
            int idx = p * 128 + tid;
            int row = idx >> 2;
            int ch  = idx & 3;
            const __half* src = Bt + (size_t)(bn + row) * K + kk0 + ch * 8;
            uint32_t dst = (uint32_t)__cvta_generic_to_shared(bs + row * 48 + ch * 8);
            asm volatile("cp.async.cg.shared.global [%0], [%1], 16;"
                         :: "r"(dst), "l"(src) : "memory");
        }
        asm volatile("cp.async.commit_group;" ::: "memory");
    };

    const int T = K >> 5;
    load_tile(0, 0);
    if (T > 1) load_tile(1, 1);

    int buf = 0;
    for (int kt = 0; kt < T; kt++) {
        if (kt + 1 < T) asm volatile("cp.async.wait_group 1;" ::: "memory");
        else            asm volatile("cp.async.wait_group 0;" ::: "memory");
        __syncthreads();

        if (kt + 2 < T) load_tile(kt + 2, (kt + 2) % 3);

        const __half* as = As(buf);
        const __half* bs = Bs(buf);

        #pragma unroll
        for (int s = 0; s < 2; s++) {
            uint32_t af[4][4];
            #pragma unroll
            for (int mt = 0; mt < 4; mt++) {
                int rb = mw * 64 + mt * 16;
                uint2 lo = *(const uint2*)(as + (rb + g)     * 48 + s * 16 + tig * 4);
                uint2 hi = *(const uint2*)(as + (rb + g + 8) * 48 + s * 16 + tig * 4);
                af[mt][0] = lo.x; af[mt][1] = hi.x; af[mt][2] = lo.y; af[mt][3] = hi.y;
            }
            #pragma unroll
            for (int nt = 0; nt < 8; nt++) {
                int cb = nw * 64 + nt * 8;
                uint2 bv = *(const uint2*)(bs + (cb + g) * 48 + s * 16 + tig * 4);
                #pragma unroll
                for (int mt = 0; mt < 4; mt++)
                    mma_f16(acc[mt][nt], af[mt][0], af[mt][1], af[mt][2], af[mt][3],
                            bv.x, bv.y);
            }
        }
        buf = (buf == 2) ? 0 : buf + 1;
    }

    // epilogue
    float* Cf = (float*)Cv;
    __half* Ch = (__half*)Cv;
    #pragma unroll
    for (int mt = 0; mt < 4; mt++) {
        int r0 = bm + mw * 64 + mt * 16 + g;
        #pragma unroll
        for (int nt = 0; nt < 8; nt++) {
            int c0 = bn + nw * 64 + nt * 8 + 2 * tig;
            float b0 = bias[c0], b1 = bias[c0 + 1];
            #pragma unroll
            for (int h = 0; h < 2; h++) {
                int row = r0 + h * 8;
                if (row >= M) continue;
                float v0 = acc[mt][nt][h * 2 + 0] + b0;
                float v1 = acc[mt][nt][h * 2 + 1] + b1;
                if (EPI == 1) {
                    v0 = 0.5f * v0 * (1.f + erff(v0 * 0.70710678118654752f));
                    v1 = 0.5f * v1 * (1.f + erff(v1 * 0.70710678118654752f));
                    int pos = il16(c0);
                    __half2 hv = __floats2half2_rn(v0, v1);
                    *(__half2*)(Ch + (size_t)row * N + pos) = hv;
                } else {
                    if (EPI == 2) {
                        const float2 rr = *(const float2*)(res + (size_t)row * N + c0);
                        v0 += rr.x; v1 += rr.y;
                    }
                    float2 o; o.x = v0; o.y = v1;
                    *(float2*)(Cf + (size_t)row * N + c0) = o;
                }
            }
        }
    }
}

// ---------------- LayerNorm: fp32 natural out (attention path) ----------------
__global__ void __launch_bounds__(256)
ln_f_kernel(const float* __restrict__ x, const float* __restrict__ g,
            const float* __restrict__ b, float* __restrict__ o)
{
    int row = blockIdx.x;
    int tid = threadIdx.x;
    const float* xr = x + (size_t)row * DMODEL;
    float v0 = xr[tid], v1 = xr[tid + 256], v2 = xr[tid + 512];

    __shared__ float red[10];
    float s = v0 + v1 + v2;
    #pragma unroll
    for (int of = 16; of; of >>= 1) s += __shfl_xor_sync(~0u, s, of);
    if ((tid & 31) == 0) red[tid >> 5] = s;
    __syncthreads();
    if (tid == 0) {
        float t = 0.f;
        #pragma unroll
        for (int i = 0; i < 8; i++) t += red[i];
        red[8] = t * (1.f / 768.f);
    }
    __syncthreads();
    float mu = red[8];
    float d0 = v0 - mu, d1 = v1 - mu, d2 = v2 - mu;
    float q = d0 * d0 + d1 * d1 + d2 * d2;
    #pragma unroll
    for (int of = 16; of; of >>= 1) q += __shfl_xor_sync(~0u, q, of);
    if ((tid & 31) == 0) red[tid >> 5] = q;
    __syncthreads();
    if (tid == 0) {
        float t = 0.f;
        #pragma unroll
        for (int i = 0; i < 8; i++) t += red[i];
        red[9] = rsqrtf(t * (1.f / 768.f) + 1e-5f);
    }
    __syncthreads();
    float inv = red[9];
    float* orow = o + (size_t)row * DMODEL;
    orow[tid]       = tf32r(d0 * inv * g[tid]       + b[tid]);
    orow[tid + 256] = tf32r(d1 * inv * g[tid + 256] + b[tid + 256]);
    orow[tid + 512] = tf32r(d2 * inv * g[tid + 512] + b[tid + 512]);
}

// ---------------- LayerNorm: fp16 interleaved out (MLP path) ----------------
__global__ void __launch_bounds__(256)
ln_h_kernel(const float* __restrict__ x, const float* __restrict__ g,
            const float* __restrict__ b, __half* __restrict__ o)
{
    int row = blockIdx.x;
    int tid = threadIdx.x;
    const float* xr = x + (size_t)row * DMODEL;
    float v0 = xr[tid], v1 = xr[tid + 256], v2 = xr[tid + 512];

    __shared__ float red[10];
    float s = v0 + v1 + v2;
    #pragma unroll
    for (int of = 16; of; of >>= 1) s += __shfl_xor_sync(~0u, s, of);
    if ((tid & 31) == 0) red[tid >> 5] = s;
    __syncthreads();
    if (tid == 0) {
        float t = 0.f;
        #pragma unroll
        for (int i = 0; i < 8; i++) t += red[i];
        red[8] = t * (1.f / 768.f);
    }
    __syncthreads();
    float mu = red[8];
    float d0 = v0 - mu, d1 = v1 - mu, d2 = v2 - mu;
    float q = d0 * d0 + d1 * d1 + d2 * d2;
    #pragma unroll
    for (int of = 16; of; of >>= 1) q += __shfl_xor_sync(~0u, q, of);
    if ((tid & 31) == 0) red[tid >> 5] = q;
    __syncthreads();
    if (tid == 0) {
        float t = 0.f;
        #pragma unroll
        for (int i = 0; i < 8; i++) t += red[i];
        red[9] = rsqrtf(t * (1.f / 768.f) + 1e-5f);
    }
    __syncthreads();
    float inv = red[9];
    __half* orow = o + (size_t)row * DMODEL;
    orow[il16(tid)]       = __float2half(d0 * inv * g[tid]       + b[tid]);
    orow[il16(tid + 256)] = __float2half(d1 * inv * g[tid + 256] + b[tid + 256]);
    orow[il16(tid + 512)] = __float2half(d2 * inv * g[tid + 512] + b[tid + 512]);
}

// ---------------- per-head QKV projection, tf32 mma (unchanged, R8) ----------------
__global__ void __launch_bounds__(128)
qkv_kernel(const float* __restrict__ h,
           const float* __restrict__ Wq, const float* __restrict__ Wk, const float* __restrict__ Wv,
           const float* __restrict__ bq, const float* __restrict__ bk, const float* __restrict__ bv,
           float* __restrict__ q, float* __restrict__ k, float* __restrict__ v)
{
    __shared__ float Xs[64][68];
    __shared__ float Ws[64][68];

    const int t0 = blockIdx.x * 64;
    const int hh = blockIdx.y;
    const int z  = blockIdx.z;
    const float* W  = ((z == 0) ? Wq : (z == 1) ? Wk : Wv) + hh * 64 * 64;
    const float* bb = ((z == 0) ? bq : (z == 1) ? bk : bv) + hh * 64;
    float* out      = (z == 0) ? q  : (z == 1) ? k  : v;

    const int tid  = threadIdx.x;
    const int wid  = tid >> 5;
    const int lane = tid & 31;
    const int g    = lane >> 2;
    const int tig  = lane & 3;
    const int rb   = wid * 16;

    #pragma unroll
    for (int it = 0; it < 8; it++) {
        int idx = it * 128 + tid;
        int row = idx >> 4;
        int col = (idx & 15) * 4;
        int tok = t0 + row;
        float4 xv = make_float4(0.f, 0.f, 0.f, 0.f);
        if (tok < NS) xv = *(const float4*)(h + (size_t)tok * DMODEL + hh * 64 + col);
        *(float4*)&Xs[row][col] = xv;
        *(float4*)&Ws[row][col] = *(const float4*)(W + row * 64 + col);
    }
    __syncthreads();

    float acc[8][4];
    #pragma unroll
    for (int nt = 0; nt < 8; nt++)
        #pragma unroll
        for (int c = 0; c < 4; c++) acc[nt][c] = 0.f;

    #pragma unroll
    for (int ks = 0; ks < 8; ks++) {
        const int kk = ks * 8;
        uint32_t a0 = __float_as_uint(Xs[rb + g]    [kk + tig]);
        uint32_t a1 = __float_as_uint(Xs[rb + g + 8][kk + tig]);
        uint32_t a2 = __float_as_uint(Xs[rb + g]    [kk + tig + 4]);
        uint32_t a3 = __float_as_uint(Xs[rb + g + 8][kk + tig + 4]);
        #pragma unroll
        for (int nt = 0; nt < 8; nt++) {
            uint32_t b0 = __float_as_uint(Ws[kk + tig]    [nt * 8 + g]);
            uint32_t b1 = __float_as_uint(Ws[kk + tig + 4][nt * 8 + g]);
            mma_tf32(acc[nt], a0, a1, a2, a3, b0, b1);
        }
    }

    #pragma unroll
    for (int nt = 0; nt < 8; nt++) {
        int col = nt * 8 + 2 * tig;
        float b0 = bb[col], b1 = bb[col + 1];
        #pragma unroll
        for (int half = 0; half < 2; half++) {
            int tok = t0 + rb + g + half * 8;
            if (tok >= NS) continue;
            float2 o;
            o.x = tf32r(acc[nt][half * 2 + 0] + b0);
            o.y = tf32r(acc[nt][half * 2 + 1] + b1);
            *(float2*)(out + (size_t)tok * DMODEL + hh * 64 + col) = o;
        }
    }
}

// ---------------- fused flash attention, tf32 mma (unchanged, R8) ----------------
#define ATTN_SMEM ((3 * 64 * 68 + 64 * 72) * 4)   // 70656 bytes

__global__ void __launch_bounds__(128)
attn_kernel(const float* __restrict__ q, const float* __restrict__ k,
            const float* __restrict__ v, float* __restrict__ x)
{
    extern __shared__ float sm[];
    float (*Qs)[68] = reinterpret_cast<float(*)[68]>(sm);
    float (*Ks)[68] = reinterpret_cast<float(*)[68]>(sm + 64 * 68);
    float (*Ps)[68] = reinterpret_cast<float(*)[68]>(sm + 2 * 64 * 68);
    float (*Vs)[72] = reinterpret_cast<float(*)[72]>(sm + 3 * 64 * 68);

    const int q0 = blockIdx.x * 64;
    const int b  = blockIdx.y;
    const int n  = b / NHEAD, hh = b - n * NHEAD;
    const int tid  = threadIdx.x;
    const int wid  = tid >> 5;
    const int lane = tid & 31;
    const int g    = lane >> 2;
    const int tig  = lane & 3;
    const int rb   = wid * 16;

    #pragma unroll
    for (int it = 0; it < 8; it++) {
        int idx = it * 128 + tid;
        int row = idx >> 4;
        int col = (idx & 15) * 4;
        int qt = q0 + row;
        float4 qv = make_float4(0.f, 0.f, 0.f, 0.f);
        if (qt < SEQ) qv = *(const float4*)(q + (size_t)(n * SEQ + qt) * DMODEL + hh * 64 + col);
        *(float4*)&Qs[row][col] = qv;
    }

    float m_run[2] = {-1e30f, -1e30f};
    float l_run[2] = {0.f, 0.f};
    float acc_o[8][4];
    #pragma unroll
    for (int nt = 0; nt < 8; nt++)
        #pragma unroll
        for (int c = 0; c < 4; c++) acc_o[nt][c] = 0.f;

    for (int kt = 0; kt < 4; kt++) {
        const int k0 = kt * 64;
        __syncthreads();

        #pragma unroll
        for (int it = 0; it < 8; it++) {
            int idx = it * 128 + tid;
            int row = idx >> 4;
            int col = (idx & 15) * 4;
            int ktok = k0 + row;
            float4 kv = make_float4(0.f, 0.f, 0.f, 0.f);
            float4 vv = make_float4(0.f, 0.f, 0.f, 0.f);
            if (ktok < SEQ) {
                kv = *(const float4*)(k + (size_t)(n * SEQ + ktok) * DMODEL + hh * 64 + col);
                vv = *(const float4*)(v + (size_t)(n * SEQ + ktok) * DMODEL + hh * 64 + col);
            }
            *(float4*)&Ks[row][col] = kv;
            *(float4*)&Vs[row][col] = vv;
        }
        __syncthreads();

        float s[8][4];
        #pragma unroll
        for (int nt = 0; nt < 8; nt++)
            #pragma unroll
            for (int c = 0; c < 4; c++) s[nt][c] = 0.f;

        #pragma unroll
        for (int ks = 0; ks < 8; ks++) {
            const int kk = ks * 8;
            uint32_t a0 = __float_as_uint(Qs[rb + g]    [kk + tig]);
            uint32_t a1 = __float_as_uint(Qs[rb + g + 8][kk + tig]);
            uint32_t a2 = __float_as_uint(Qs[rb + g]    [kk + tig + 4]);
            uint32_t a3 = __float_as_uint(Qs[rb + g + 8][kk + tig + 4]);
            #pragma unroll
            for (int nt = 0; nt < 8; nt++) {
                uint32_t b0 = __float_as_uint(Ks[nt * 8 + g][kk + tig]);
                uint32_t b1 = __float_as_uint(Ks[nt * 8 + g][kk + tig + 4]);
                mma_tf32(s[nt], a0, a1, a2, a3, b0, b1);
            }
        }

        #pragma unroll
        for (int nt = 0; nt < 8; nt++) {
            int c0 = k0 + nt * 8 + 2 * tig;
            s[nt][0] = (c0     < SEQ) ? s[nt][0] * 0.125f : -1e30f;
            s[nt][1] = (c0 + 1 < SEQ) ? s[nt][1] * 0.125f : -1e30f;
            s[nt][2] = (c0     < SEQ) ? s[nt][2] * 0.125f : -1e30f;
            s[nt][3] = (c0 + 1 < SEQ) ? s[nt][3] * 0.125f : -1e30f;
        }

        #pragma unroll
        for (int r = 0; r < 2; r++) {
            float mt_ = -1e30f;
            #pragma unroll
            for (int nt = 0; nt < 8; nt++)
                mt_ = fmaxf(mt_, fmaxf(s[nt][2 * r], s[nt][2 * r + 1]));
            mt_ = fmaxf(mt_, __shfl_xor_sync(~0u, mt_, 1));
            mt_ = fmaxf(mt_, __shfl_xor_sync(~0u, mt_, 2));
            float mnew = fmaxf(m_run[r], mt_);
            float sc = expf(m_run[r] - mnew);
            float rs = 0.f;
            #pragma unroll
            for (int nt = 0; nt < 8; nt++) {
                float p0 = expf(s[nt][2 * r]     - mnew);
                float p1 = expf(s[nt][2 * r + 1] - mnew);
                s[nt][2 * r] = p0; s[nt][2 * r + 1] = p1;
                rs += p0 + p1;
            }
            rs += __shfl_xor_sync(~0u, rs, 1);
            rs += __shfl_xor_sync(~0u, rs, 2);
            l_run[r] = l_run[r] * sc + rs;
            #pragma unroll
            for (int nt = 0; nt < 8; nt++) {
                acc_o[nt][2 * r]     *= sc;
                acc_o[nt][2 * r + 1] *= sc;
            }
            m_run[r] = mnew;
        }

        #pragma unroll
        for (int nt = 0; nt < 8; nt++) {
            float2 p0; p0.x = tf32r(s[nt][0]); p0.y = tf32r(s[nt][1]);
            float2 p1; p1.x = tf32r(s[nt][2]); p1.y = tf32r(s[nt][3]);
            *(float2*)&Ps[rb + g]    [nt * 8 + 2 * tig] = p0;
            *(float2*)&Ps[rb + g + 8][nt * 8 + 2 * tig] = p1;
        }
        __syncwarp();

        #pragma unroll
        for (int ks = 0; ks < 8; ks++) {
            const int kk = ks * 8;
            uint32_t a0 = __float_as_uint(Ps[rb + g]    [kk + tig]);
            uint32_t a1 = __float_as_uint(Ps[rb + g + 8][kk + tig]);
            uint32_t a2 = __float_as_uint(Ps[rb + g]    [kk + tig + 4]);
            uint32_t a3 = __float_as_uint(Ps[rb + g + 8][kk + tig + 4]);
            #pragma unroll
            for (int nt = 0; nt < 8; nt++) {
                uint32_t b0 = __float_as_uint(Vs[kk + tig]    [nt * 8 + g]);
                uint32_t b1 = __float_as_uint(Vs[kk + tig + 4][nt * 8 + g]);
                mma_tf32(acc_o[nt], a0, a1, a2, a3, b0, b1);
            }
        }
    }

    #pragma unroll
    for (int r = 0; r < 2; r++) {
        int row = q0 + rb + g + r * 8;
        if (row >= SEQ) continue;
        float inv = 1.f / l_run[r];
        #pragma unroll
        for (int nt = 0; nt < 8; nt++) {
            int col = hh * 64 + nt * 8 + 2 * tig;
            float* px = x + (size_t)(n * SEQ + row) * DMODEL + col;
            float2 old = *(float2*)px;
            old.x += acc_o[nt][2 * r]     * inv;
            old.y += acc_o[nt][2 * r + 1] * inv;
            *(float2*)px = old;
        }
    }
}

// ---------------- head + softmax ----------------
__global__ void __launch_bounds__(256)
head_kernel(const float* __restrict__ x, const float* __restrict__ Wh,
            const float* __restrict__ bh, float* __restrict__ out)
{
    __shared__ float xs[DMODEL];
    __shared__ float lg[OUTD];
    __shared__ float red[256];
    int n = blockIdx.x, tid = threadIdx.x;
    for (int i = tid; i < DMODEL; i += 256) xs[i] = x[(size_t)n * SEQ * DMODEL + i];
    __syncthreads();
    for (int o = tid; o < OUTD; o += 256) {
        float a = bh[o];
        for (int kk = 0; kk < DMODEL; kk++)
            a = fmaf(xs[kk], Wh[(size_t)kk * OUTD + o], a);
        lg[o] = a;
    }
    __syncthreads();
    float m = -1e30f;
    for (int o = tid; o < OUTD; o += 256) m = fmaxf(m, lg[o]);
    red[tid] = m; __syncthreads();
    for (int s = 128; s; s >>= 1) { if (tid < s) red[tid] = fmaxf(red[tid], red[tid + s]); __syncthreads(); }
    float mx = red[0]; __syncthreads();
    float sm = 0.f;
    for (int o = tid; o < OUTD; o += 256) sm += expf(lg[o] - mx);
    red[tid] = sm; __syncthreads();
    for (int s = 128; s; s >>= 1) { if (tid < s) red[tid] += red[tid + s]; __syncthreads(); }
    float inv = 1.f / red[0];
    __syncthreads();
    for (int o = tid; o < OUTD; o += 256)
        out[(size_t)n * OUTD + o] = expf(lg[o] - mx) * inv;
}

// ---------------- host orchestration ----------------
extern "C" void kernel_launch(void* const* d_in, const int* in_sizes, int n_in,
                              void* d_out, int out_size)
{
    const float* images   = (const float*)d_in[0];
    const float* W_map    = (const float*)d_in[1];
    const float* b_map    = (const float*)d_in[2];
    const float* cls      = (const float*)d_in[3];
    const float* pos      = (const float*)d_in[4];
    const float* ln1_g    = (const float*)d_in[5];
    const float* ln1_b    = (const float*)d_in[6];
    const float* Wq       = (const float*)d_in[7];
    const float* bq       = (const float*)d_in[8];
    const float* Wk       = (const float*)d_in[9];
    const float* bk       = (const float*)d_in[10];
    const float* Wv       = (const float*)d_in[11];
    const float* bv       = (const float*)d_in[12];
    const float* ln2_g    = (const float*)d_in[13];
    const float* ln2_b    = (const float*)d_in[14];
    const float* W1       = (const float*)d_in[15];
    const float* b1       = (const float*)d_in[16];
    const float* W2       = (const float*)d_in[17];
    const float* b2       = (const float*)d_in[18];
    const float* W_head   = (const float*)d_in[19];
    const float* b_head   = (const float*)d_in[20];
    float* out = (float*)d_out;

    __half *p_patches16, *p_h16, *p_mlp16, *p_wmapT16, *p_w1T16, *p_w2T16;
    float *p_tokens, *p_x, *p_hf, *p_q, *p_k, *p_v, *p_wq, *p_wk, *p_wv;
    cudaGetSymbolAddress((void**)&p_patches16, g_patches16);
    cudaGetSymbolAddress((void**)&p_tokens, g_tokens);
    cudaGetSymbolAddress((void**)&p_x, g_x);
    cudaGetSymbolAddress((void**)&p_hf, g_hf);
    cudaGetSymbolAddress((void**)&p_h16, g_h16);
    cudaGetSymbolAddress((void**)&p_q, g_q);
    cudaGetSymbolAddress((void**)&p_k, g_k);
    cudaGetSymbolAddress((void**)&p_v, g_v);
    cudaGetSymbolAddress((void**)&p_mlp16, g_mlp16);
    cudaGetSymbolAddress((void**)&p_wmapT16, g_wmapT16);
    cudaGetSymbolAddress((void**)&p_w1T16, g_w1T16);
    cudaGetSymbolAddress((void**)&p_w2T16, g_w2T16);
    cudaGetSymbolAddress((void**)&p_wq, g_wq);
    cudaGetSymbolAddress((void**)&p_wk, g_wk);
    cudaGetSymbolAddress((void**)&p_wv, g_wv);

    cudaFuncSetAttribute(tgemm16<0>, cudaFuncAttributeMaxDynamicSharedMemorySize, TG16_SMEM);
    cudaFuncSetAttribute(tgemm16<1>, cudaFuncAttributeMaxDynamicSharedMemorySize, TG16_SMEM);
    cudaFuncSetAttribute(tgemm16<2>, cudaFuncAttributeMaxDynamicSharedMemorySize, TG16_SMEM);
    cudaFuncSetAttribute(attn_kernel, cudaFuncAttributeMaxDynamicSharedMemorySize, ATTN_SMEM);

    // 0) weight prep
    {
        dim3 gmap(DMODEL / 32, IN_DIM / 32, 1);
        cvtT16_kernel<<<gmap, 256>>>(W_map, p_wmapT16, IN_DIM, DMODEL);
        dim3 g1(MLPD / 32, DMODEL / 32, LAYERS);
        cvtT16_kernel<<<g1, 256>>>(W1, p_w1T16, DMODEL, MLPD);
        dim3 g2(DMODEL / 32, MLPD / 32, LAYERS);
        cvtT16_kernel<<<g2, 256>>>(W2, p_w2T16, MLPD, DMODEL);
        int n4 = LAYERS * NHEAD * DHEAD * DHEAD / 4;
        cvt_kernel<<<(n4 + 255) / 256, 256>>>(Wq, p_wq, n4);
        cvt_kernel<<<(n4 + 255) / 256, 256>>>(Wk, p_wk, n4);
        cvt_kernel<<<(n4 + 255) / 256, 256>>>(Wv, p_wv, n4);
    }

    // 1) patchify + embed + assemble
    patchify_kernel<<<(NP * IN_DIM) / 256, 256>>>(images);
    {
        dim3 grid(DMODEL / 128, NP / 128);   // 6 x 49
        tgemm16<0><<<grid, 128, TG16_SMEM>>>(p_patches16, p_wmapT16, b_map, nullptr,
                                             p_tokens, NP, DMODEL, IN_DIM);
    }
    assemble_kernel<<<(NS * DMODEL) / 256, 256>>>(p_tokens, cls, pos);

    // 2) transformer blocks
    for (int l = 0; l < LAYERS; l++) {
        ln_f_kernel<<<NS, 256>>>(p_x, ln1_g + l * DMODEL, ln1_b + l * DMODEL, p_hf);

        {
            dim3 grid((NS + 63) / 64, NHEAD, 3);
            qkv_kernel<<<grid, 128>>>(p_hf,
                p_wq + (size_t)l * NHEAD * DHEAD * DHEAD,
                p_wk + (size_t)l * NHEAD * DHEAD * DHEAD,
                p_wv + (size_t)l * NHEAD * DHEAD * DHEAD,
                bq + (size_t)l * NHEAD * DHEAD,
                bk + (size_t)l * NHEAD * DHEAD,
                bv + (size_t)l * NHEAD * DHEAD,
                p_q, p_k, p_v);
        }
        {
            dim3 grid((SEQ + 63) / 64, NB * NHEAD);
            attn_kernel<<<grid, 128, ATTN_SMEM>>>(p_q, p_k, p_v, p_x);
        }

        ln_h_kernel<<<NS, 256>>>(p_x, ln2_g + l * DMODEL, ln2_b + l * DMODEL, p_h16);
        {
            dim3 grid(MLPD / 128, (NS + 127) / 128);   // 24 x 50
            tgemm16<1><<<grid, 128, TG16_SMEM>>>(p_h16, p_w1T16 + (size_t)l * DMODEL * MLPD,
                                                 b1 + (size_t)l * MLPD, nullptr,
                                                 p_mlp16, NS, MLPD, DMODEL);
        }
        {
            dim3 grid(DMODEL / 128, (NS + 127) / 128); // 6 x 50
            tgemm16<2><<<grid, 128, TG16_SMEM>>>(p_mlp16, p_w2T16 + (size_t)l * MLPD * DMODEL,
                                                 b2 + (size_t)l * DMODEL, p_x,
                                                 p_x, NS, DMODEL, MLPD);
        }
    }

    // 3) head + softmax
    head_kernel<<<NB, 256>>>(p_x, W_head, b_head, out);
}

// round 11
// speedup vs baseline: 3.9156x; 1.1277x over previous
#include <cuda_runtime.h>
#include <cuda_bf16.h>
#include <cuda_fp16.h>
#include <math.h>
#include <cstdint>

// ---------------- problem constants ----------------
#define NB     32
#define SEQ    197
#define SEQP   256
#define DMODEL 768
#define NHEAD  12
#define DHEAD  64
#define LAYERS 12
#define MLPD   3072
#define OUTD   1000
#define PPATCH 196
#define IN_DIM 768
#define NS     (NB * SEQ)       // 6304 tokens
#define NP     (NB * PPATCH)    // 6272 patches

// ---------------- device scratch ----------------
__device__ __half g_patches16[NP * IN_DIM];        // embed A (fp16, k-interleaved)
__device__ float  g_tokens[NP * DMODEL];           // embed output (fp32)
__device__ float  g_x[NS * DMODEL];                // residual stream (fp32)
__device__ __half g_h16[NS * DMODEL];              // LN out (fp16, interleaved) - shared ln1/ln2
__device__ __half g_q16[NS * DMODEL];              // Q (fp16, e-interleaved per head)
__device__ __half g_k16[NS * DMODEL];              // K (fp16, e-interleaved per head)
__device__ __half g_vT16[NB * NHEAD * 64 * SEQP];  // V transposed [b][e][key] key-interleaved
__device__ __half g_mlp16[NS * MLPD];              // MLP1 out (fp16, interleaved)
// weights (fp16, transposed [N][K], K interleaved)
__device__ __half g_wmapT16[DMODEL * IN_DIM];
__device__ __half g_w1T16[LAYERS * MLPD * DMODEL];
__device__ __half g_w2T16[LAYERS * DMODEL * MLPD];
__device__ __half g_wqT16[LAYERS * NHEAD * DHEAD * DHEAD];
__device__ __half g_wkT16[LAYERS * NHEAD * DHEAD * DHEAD];
__device__ __half g_wvT16[LAYERS * NHEAD * DHEAD * DHEAD];

// k-interleave within 16-groups: perm = [0,1,4,5,8,9,12,13,2,3,6,7,10,11,14,15]
__device__ __forceinline__ int il16(int c)
{
    int r = c & 15;
    int p = ((r & 7) >> 1) * 4 + ((r >> 3) << 1) + (r & 1);
    return (c & ~15) | p;
}
__device__ __forceinline__ int inv16(int c)
{
    int r = c & 15;
    int k = (((r & 3) < 2) ? 0 : 8) + ((r >> 2) << 1) + (r & 1);
    return (c & ~15) | k;
}

__device__ __forceinline__ void mma_f16(float* c, uint32_t a0, uint32_t a1,
                                        uint32_t a2, uint32_t a3,
                                        uint32_t b0, uint32_t b1)
{
    asm volatile(
        "mma.sync.aligned.m16n8k16.row.col.f32.f16.f16.f32 "
        "{%0,%1,%2,%3},{%4,%5,%6,%7},{%8,%9},{%0,%1,%2,%3};"
        : "+f"(c[0]), "+f"(c[1]), "+f"(c[2]), "+f"(c[3])
        : "r"(a0), "r"(a1), "r"(a2), "r"(a3), "r"(b0), "r"(b1));
}

// ---------------- weight prep: fp16 + transpose src[R][C] -> dst[C][R], R interleaved ----
__global__ void __launch_bounds__(256)
cvtT16_kernel(const float* __restrict__ src, __half* __restrict__ dst, int R, int C)
{
    __shared__ float t[32][33];
    size_t zoff = (size_t)blockIdx.z * R * C;
    int bx = blockIdx.x * 32;
    int by = blockIdx.y * 32;
    int tx = threadIdx.x & 31;
    int ty = threadIdx.x >> 5;
    #pragma unroll
    for (int i = 0; i < 32; i += 8)
        t[ty + i][tx] = src[zoff + (size_t)(by + ty + i) * C + bx + tx];
    __syncthreads();
    int kp = il16(by + tx);
    #pragma unroll
    for (int i = 0; i < 32; i += 8)
        dst[zoff + (size_t)(bx + ty + i) * R + kp] = __float2half(t[tx][ty + i]);
}

// ---------------- patchify (fp16, k-interleaved) ----------------
__global__ void __launch_bounds__(256)
patchify_kernel(const float* __restrict__ img)
{
    int idx = blockIdx.x * 256 + threadIdx.x;
    if (idx >= NP * IN_DIM) return;
    int t = idx / IN_DIM;
    int ep = idx - t * IN_DIM;
    int e = inv16(ep);
    int n = t / PPATCH;
    int p = t - n * PPATCH;
    int py = p / 14, px = p - py * 14;
    int c  = e >> 8;
    int r  = e & 255;
    int ph = r >> 4, pw = r & 15;
    g_patches16[idx] = __float2half(
        img[(((size_t)n * 3 + c) * 224 + (py * 16 + ph)) * 224 + px * 16 + pw]);
}

// ---------------- assemble ----------------
__global__ void __launch_bounds__(256)
assemble_kernel(const float* __restrict__ tokens, const float* __restrict__ cls,
                const float* __restrict__ pos)
{
    int idx = blockIdx.x * 256 + threadIdx.x;
    if (idx >= NS * DMODEL) return;
    int t = idx / DMODEL;
    int d = idx - t * DMODEL;
    int n = t / SEQ;
    int s = t - n * SEQ;
    float v = (s == 0) ? cls[d] : tokens[((size_t)(n * PPATCH + s - 1)) * DMODEL + d];
    g_x[idx] = v + pos[s * DMODEL + d];
}

// ---------------- fp16 tensor-core GEMM (proven R10 kernel) ----------
#define TG16_STAGE 24576
#define TG16_SMEM  (3 * TG16_STAGE)   // 73728 bytes

template<int EPI>
__global__ void __launch_bounds__(128, 2)
tgemm16(const __half* __restrict__ A, const __half* __restrict__ Bt,
        const float* __restrict__ bias, const float* __restrict__ res,
        void* __restrict__ Cv, int M, int N, int K)
{
    extern __shared__ char sm16[];

    const int tid  = threadIdx.x;
    const int wid  = tid >> 5;
    const int lane = tid & 31;
    const int g    = lane >> 2;
    const int tig  = lane & 3;
    const int mw   = wid & 1;
    const int nw   = wid >> 1;
    const int bm   = blockIdx.y * 128;
    const int bn   = blockIdx.x * 128;

    float acc[4][8][4];
    #pragma unroll
    for (int i = 0; i < 4; i++)
        #pragma unroll
        for (int j = 0; j < 8; j++)
            #pragma unroll
            for (int c = 0; c < 4; c++) acc[i][j][c] = 0.f;

    auto As = [&](int buf) { return (__half*)(sm16 + buf * TG16_STAGE); };
    auto Bs = [&](int buf) { return (__half*)(sm16 + buf * TG16_STAGE + 12288); };

    auto load_tile = [&](int kt, int buf) {
        __half* as = As(buf);
        __half* bs = Bs(buf);
        const int kk0 = kt * 32;
        #pragma unroll
        for (int p = 0; p < 4; p++) {
            int idx = p * 128 + tid;
            int row = idx >> 2;
            int ch  = idx & 3;
            const __half* src = A + (size_t)(bm + row) * K + kk0 + ch * 8;
            uint32_t dst = (uint32_t)__cvta_generic_to_shared(as + row * 48 + ch * 8);
            int sz = (bm + row) < M ? 16 : 0;
            asm volatile("cp.async.cg.shared.global [%0], [%1], 16, %2;"
                         :: "r"(dst), "l"(src), "r"(sz) : "memory");
        }
        #pragma unroll
        for (int p = 0; p < 4; p++) {
            int idx = p * 128 + tid;
            int row = idx >> 2;
            int ch  = idx & 3;
            const __half* src = Bt + (size_t)(bn + row) * K + kk0 + ch * 8;
            uint32_t dst = (uint32_t)__cvta_generic_to_shared(bs + row * 48 + ch * 8);
            asm volatile("cp.async.cg.shared.global [%0], [%1], 16;"
                         :: "r"(dst), "l"(src) : "memory");
        }
        asm volatile("cp.async.commit_group;" ::: "memory");
    };

    const int T = K >> 5;
    load_tile(0, 0);
    if (T > 1) load_tile(1, 1);

    int buf = 0;
    for (int kt = 0; kt < T; kt++) {
        if (kt + 1 < T) asm volatile("cp.async.wait_group 1;" ::: "memory");
        else            asm volatile("cp.async.wait_group 0;" ::: "memory");
        __syncthreads();

        if (kt + 2 < T) load_tile(kt + 2, (kt + 2) % 3);

        const __half* as = As(buf);
        const __half* bs = Bs(buf);

        #pragma unroll
        for (int s = 0; s < 2; s++) {
            uint32_t af[4][4];
            #pragma unroll
            for (int mt = 0; mt < 4; mt++) {
                int rb = mw * 64 + mt * 16;
                uint2 lo = *(const uint2*)(as + (rb + g)     * 48 + s * 16 + tig * 4);
                uint2 hi = *(const uint2*)(as + (rb + g + 8) * 48 + s * 16 + tig * 4);
                af[mt][0] = lo.x; af[mt][1] = hi.x; af[mt][2] = lo.y; af[mt][3] = hi.y;
            }
            #pragma unroll
            for (int nt = 0; nt < 8; nt++) {
                int cb = nw * 64 + nt * 8;
                uint2 bv = *(const uint2*)(bs + (cb + g) * 48 + s * 16 + tig * 4);
                #pragma unroll
                for (int mt = 0; mt < 4; mt++)
                    mma_f16(acc[mt][nt], af[mt][0], af[mt][1], af[mt][2], af[mt][3],
                            bv.x, bv.y);
            }
        }
        buf = (buf == 2) ? 0 : buf + 1;
    }

    float* Cf = (float*)Cv;
    __half* Ch = (__half*)Cv;
    #pragma unroll
    for (int mt = 0; mt < 4; mt++) {
        int r0 = bm + mw * 64 + mt * 16 + g;
        #pragma unroll
        for (int nt = 0; nt < 8; nt++) {
            int c0 = bn + nw * 64 + nt * 8 + 2 * tig;
            float b0 = bias[c0], b1 = bias[c0 + 1];
            #pragma unroll
            for (int h = 0; h < 2; h++) {
                int row = r0 + h * 8;
                if (row >= M) continue;
                float v0 = acc[mt][nt][h * 2 + 0] + b0;
                float v1 = acc[mt][nt][h * 2 + 1] + b1;
                if (EPI == 1) {
                    v0 = 0.5f * v0 * (1.f + erff(v0 * 0.70710678118654752f));
                    v1 = 0.5f * v1 * (1.f + erff(v1 * 0.70710678118654752f));
                    int pos = il16(c0);
                    __half2 hv = __floats2half2_rn(v0, v1);
                    *(__half2*)(Ch + (size_t)row * N + pos) = hv;
                } else {
                    if (EPI == 2) {
                        const float2 rr = *(const float2*)(res + (size_t)row * N + c0);
                        v0 += rr.x; v1 += rr.y;
                    }
                    float2 o; o.x = v0; o.y = v1;
                    *(float2*)(Cf + (size_t)row * N + c0) = o;
                }
            }
        }
    }
}

// ---------------- LayerNorm: fp16 interleaved out ----------------
__global__ void __launch_bounds__(256)
ln_h_kernel(const float* __restrict__ x, const float* __restrict__ g,
            const float* __restrict__ b, __half* __restrict__ o)
{
    int row = blockIdx.x;
    int tid = threadIdx.x;
    const float* xr = x + (size_t)row * DMODEL;
    float v0 = xr[tid], v1 = xr[tid + 256], v2 = xr[tid + 512];

    __shared__ float red[10];
    float s = v0 + v1 + v2;
    #pragma unroll
    for (int of = 16; of; of >>= 1) s += __shfl_xor_sync(~0u, s, of);
    if ((tid & 31) == 0) red[tid >> 5] = s;
    __syncthreads();
    if (tid == 0) {
        float t = 0.f;
        #pragma unroll
        for (int i = 0; i < 8; i++) t += red[i];
        red[8] = t * (1.f / 768.f);
    }
    __syncthreads();
    float mu = red[8];
    float d0 = v0 - mu, d1 = v1 - mu, d2 = v2 - mu;
    float q = d0 * d0 + d1 * d1 + d2 * d2;
    #pragma unroll
    for (int of = 16; of; of >>= 1) q += __shfl_xor_sync(~0u, q, of);
    if ((tid & 31) == 0) red[tid >> 5] = q;
    __syncthreads();
    if (tid == 0) {
        float t = 0.f;
        #pragma unroll
        for (int i = 0; i < 8; i++) t += red[i];
        red[9] = rsqrtf(t * (1.f / 768.f) + 1e-5f);
    }
    __syncthreads();
    float inv = red[9];
    __half* orow = o + (size_t)row * DMODEL;
    orow[il16(tid)]       = __float2half(d0 * inv * g[tid]       + b[tid]);
    orow[il16(tid + 256)] = __float2half(d1 * inv * g[tid + 256] + b[tid + 256]);
    orow[il16(tid + 512)] = __float2half(d2 * inv * g[tid + 512] + b[tid + 512]);
}

// ---------------- per-head QKV projection, fp16 mma ----------------
// Block 128 threads (4 warps), tile 64 tokens x 64 out, K=64. z: 0=Q, 1=K, 2=V(transposed out)
__global__ void __launch_bounds__(128)
qkv16_kernel(const __half* __restrict__ h,
             const __half* __restrict__ Wq, const __half* __restrict__ Wk,
             const __half* __restrict__ Wv,
             const float* __restrict__ bq, const float* __restrict__ bk,
             const float* __restrict__ bv,
             __half* __restrict__ q, __half* __restrict__ k, __half* __restrict__ vT)
{
    __shared__ __half Xs[64][80];
    __shared__ __half Ws[64][80];

    const int t0 = blockIdx.x * 64;
    const int hh = blockIdx.y;
    const int z  = blockIdx.z;
    const __half* W = ((z == 0) ? Wq : (z == 1) ? Wk : Wv) + hh * 64 * 64;
    const float* bb = ((z == 0) ? bq : (z == 1) ? bk : bv) + hh * 64;

    const int tid  = threadIdx.x;
    const int wid  = tid >> 5;
    const int lane = tid & 31;
    const int g    = lane >> 2;
    const int tig  = lane & 3;
    const int rb   = wid * 16;

    #pragma unroll
    for (int it = 0; it < 4; it++) {
        int idx = it * 128 + tid;
        int row = idx >> 3;
        int ch  = idx & 7;
        int tok = t0 + row;
        uint4 xv = make_uint4(0u, 0u, 0u, 0u);
        if (tok < NS) xv = *(const uint4*)(h + (size_t)tok * DMODEL + hh * 64 + ch * 8);
        *(uint4*)&Xs[row][ch * 8] = xv;
        *(uint4*)&Ws[row][ch * 8] = *(const uint4*)(W + row * 64 + ch * 8);
    }
    __syncthreads();

    float acc[8][4];
    #pragma unroll
    for (int nt = 0; nt < 8; nt++)
        #pragma unroll
        for (int c = 0; c < 4; c++) acc[nt][c] = 0.f;

    #pragma unroll
    for (int s = 0; s < 4; s++) {
        uint2 lo = *(const uint2*)&Xs[rb + g]    [s * 16 + tig * 4];
        uint2 hi = *(const uint2*)&Xs[rb + g + 8][s * 16 + tig * 4];
        #pragma unroll
        for (int nt = 0; nt < 8; nt++) {
            uint2 bv = *(const uint2*)&Ws[nt * 8 + g][s * 16 + tig * 4];
            mma_f16(acc[nt], lo.x, hi.x, lo.y, hi.y, bv.x, bv.y);
        }
    }

    __half* out = (z == 0) ? q : k;
    #pragma unroll
    for (int nt = 0; nt < 8; nt++) {
        int c0 = nt * 8 + 2 * tig;
        float b0 = bb[c0], b1 = bb[c0 + 1];
        #pragma unroll
        for (int hlf = 0; hlf < 2; hlf++) {
            int tok = t0 + rb + g + hlf * 8;
            if (tok >= NS) continue;
            float v0 = acc[nt][hlf * 2 + 0] + b0;
            float v1 = acc[nt][hlf * 2 + 1] + b1;
            if (z < 2) {
                __half2 hv = __floats2half2_rn(v0, v1);
                *(__half2*)(out + (size_t)tok * DMODEL + hh * 64 + il16(c0)) = hv;
            } else {
                int n  = tok / SEQ;
                int s_ = tok - n * SEQ;
                int b  = n * NHEAD + hh;
                int kp = il16(s_);
                vT[((size_t)b * 64 + c0)     * SEQP + kp] = __float2half(v0);
                vT[((size_t)b * 64 + c0 + 1) * SEQP + kp] = __float2half(v1);
            }
        }
    }
}

// ---------------- fused flash attention, fp16 mma ----------------
__global__ void __launch_bounds__(128)
attn16_kernel(const __half* __restrict__ q, const __half* __restrict__ k,
              const __half* __restrict__ vT, float* __restrict__ x)
{
    __shared__ __half Qs[64][80];
    __shared__ __half Ks[64][80];
    __shared__ __half Ps[64][80];
    __shared__ __half Vs[64][80];

    const int q0 = blockIdx.x * 64;
    const int b  = blockIdx.y;
    const int n  = b / NHEAD, hh = b - n * NHEAD;
    const int tid  = threadIdx.x;
    const int wid  = tid >> 5;
    const int lane = tid & 31;
    const int g    = lane >> 2;
    const int tig  = lane & 3;
    const int rb   = wid * 16;

    #pragma unroll
    for (int it = 0; it < 4; it++) {
        int idx = it * 128 + tid;
        int row = idx >> 3;
        int ch  = idx & 7;
        int qt = q0 + row;
        uint4 qv = make_uint4(0u, 0u, 0u, 0u);
        if (qt < SEQ) qv = *(const uint4*)(q + (size_t)(n * SEQ + qt) * DMODEL + hh * 64 + ch * 8);
        *(uint4*)&Qs[row][ch * 8] = qv;
    }

    float m_run[2] = {-1e30f, -1e30f};
    float l_run[2] = {0.f, 0.f};
    float acc_o[8][4];
    #pragma unroll
    for (int nt = 0; nt < 8; nt++)
        #pragma unroll
        for (int c = 0; c < 4; c++) acc_o[nt][c] = 0.f;

    for (int kt = 0; kt < 4; kt++) {
        const int k0 = kt * 64;
        __syncthreads();

        #pragma unroll
        for (int it = 0; it < 4; it++) {
            int idx = it * 128 + tid;
            int row = idx >> 3;
            int ch  = idx & 7;
            int ktok = k0 + row;
            uint4 kv = make_uint4(0u, 0u, 0u, 0u);
            if (ktok < SEQ)
                kv = *(const uint4*)(k + (size_t)(n * SEQ + ktok) * DMODEL + hh * 64 + ch * 8);
            *(uint4*)&Ks[row][ch * 8] = kv;
            // V^T tile: rows = e, cols = key (pre-interleaved in gmem)
            *(uint4*)&Vs[row][ch * 8] =
                *(const uint4*)(vT + ((size_t)b * 64 + row) * SEQP + k0 + ch * 8);
        }
        __syncthreads();

        float s[8][4];
        #pragma unroll
        for (int nt = 0; nt < 8; nt++)
            #pragma unroll
            for (int c = 0; c < 4; c++) s[nt][c] = 0.f;

        #pragma unroll
        for (int ss = 0; ss < 4; ss++) {
            uint2 lo = *(const uint2*)&Qs[rb + g]    [ss * 16 + tig * 4];
            uint2 hi = *(const uint2*)&Qs[rb + g + 8][ss * 16 + tig * 4];
            #pragma unroll
            for (int nt = 0; nt < 8; nt++) {
                uint2 bv = *(const uint2*)&Ks[nt * 8 + g][ss * 16 + tig * 4];
                mma_f16(s[nt], lo.x, hi.x, lo.y, hi.y, bv.x, bv.y);
            }
        }

        // scale + key mask (overwrites, so garbage in padded keys is squashed)
        #pragma unroll
        for (int nt = 0; nt < 8; nt++) {
            int c0 = k0 + nt * 8 + 2 * tig;
            s[nt][0] = (c0     < SEQ) ? s[nt][0] * 0.125f : -1e30f;
            s[nt][1] = (c0 + 1 < SEQ) ? s[nt][1] * 0.125f : -1e30f;
            s[nt][2] = (c0     < SEQ) ? s[nt][2] * 0.125f : -1e30f;
            s[nt][3] = (c0 + 1 < SEQ) ? s[nt][3] * 0.125f : -1e30f;
        }

        // online softmax (row0 = rb+g: c0,c1; row1 = rb+g+8: c2,c3)
        #pragma unroll
        for (int r = 0; r < 2; r++) {
            float mt_ = -1e30f;
            #pragma unroll
            for (int nt = 0; nt < 8; nt++)
                mt_ = fmaxf(mt_, fmaxf(s[nt][2 * r], s[nt][2 * r + 1]));
            mt_ = fmaxf(mt_, __shfl_xor_sync(~0u, mt_, 1));
            mt_ = fmaxf(mt_, __shfl_xor_sync(~0u, mt_, 2));
            float mnew = fmaxf(m_run[r], mt_);
            float sc = expf(m_run[r] - mnew);
            float rs = 0.f;
            #pragma unroll
            for (int nt = 0; nt < 8; nt++) {
                float p0 = expf(s[nt][2 * r]     - mnew);
                float p1 = expf(s[nt][2 * r + 1] - mnew);
                s[nt][2 * r] = p0; s[nt][2 * r + 1] = p1;
                rs += p0 + p1;
            }
            rs += __shfl_xor_sync(~0u, rs, 1);
            rs += __shfl_xor_sync(~0u, rs, 2);
            l_run[r] = l_run[r] * sc + rs;
            #pragma unroll
            for (int nt = 0; nt < 8; nt++) {
                acc_o[nt][2 * r]     *= sc;
                acc_o[nt][2 * r + 1] *= sc;
            }
            m_run[r] = mnew;
        }

        // stage P (fp16, key-interleaved)
        #pragma unroll
        for (int nt = 0; nt < 8; nt++) {
            int pc = il16(nt * 8 + 2 * tig);
            *(__half2*)&Ps[rb + g]    [pc] = __floats2half2_rn(s[nt][0], s[nt][1]);
            *(__half2*)&Ps[rb + g + 8][pc] = __floats2half2_rn(s[nt][2], s[nt][3]);
        }
        __syncwarp();

        // O += P @ V  (A = P [q][key], B = Vs [e][key])
        #pragma unroll
        for (int ss = 0; ss < 4; ss++) {
            uint2 lo = *(const uint2*)&Ps[rb + g]    [ss * 16 + tig * 4];
            uint2 hi = *(const uint2*)&Ps[rb + g + 8][ss * 16 + tig * 4];
            #pragma unroll
            for (int nt = 0; nt < 8; nt++) {
                uint2 bv = *(const uint2*)&Vs[nt * 8 + g][ss * 16 + tig * 4];
                mma_f16(acc_o[nt], lo.x, hi.x, lo.y, hi.y, bv.x, bv.y);
            }
        }
    }

    #pragma unroll
    for (int r = 0; r < 2; r++) {
        int row = q0 + rb + g + r * 8;
        if (row >= SEQ) continue;
        float inv = 1.f / l_run[r];
        #pragma unroll
        for (int nt = 0; nt < 8; nt++) {
            int col = hh * 64 + nt * 8 + 2 * tig;
            float* px = x + (size_t)(n * SEQ + row) * DMODEL + col;
            float2 old = *(float2*)px;
            old.x += acc_o[nt][2 * r]     * inv;
            old.y += acc_o[nt][2 * r + 1] * inv;
            *(float2*)px = old;
        }
    }
}

// ---------------- head + softmax ----------------
__global__ void __launch_bounds__(256)
head_kernel(const float* __restrict__ x, const float* __restrict__ Wh,
            const float* __restrict__ bh, float* __restrict__ out)
{
    __shared__ float xs[DMODEL];
    __shared__ float lg[OUTD];
    __shared__ float red[256];
    int n = blockIdx.x, tid = threadIdx.x;
    for (int i = tid; i < DMODEL; i += 256) xs[i] = x[(size_t)n * SEQ * DMODEL + i];
    __syncthreads();
    for (int o = tid; o < OUTD; o += 256) {
        float a = bh[o];
        for (int kk = 0; kk < DMODEL; kk++)
            a = fmaf(xs[kk], Wh[(size_t)kk * OUTD + o], a);
        lg[o] = a;
    }
    __syncthreads();
    float m = -1e30f;
    for (int o = tid; o < OUTD; o += 256) m = fmaxf(m, lg[o]);
    red[tid] = m; __syncthreads();
    for (int s = 128; s; s >>= 1) { if (tid < s) red[tid] = fmaxf(red[tid], red[tid + s]); __syncthreads(); }
    float mx = red[0]; __syncthreads();
    float sm = 0.f;
    for (int o = tid; o < OUTD; o += 256) sm += expf(lg[o] - mx);
    red[tid] = sm; __syncthreads();
    for (int s = 128; s; s >>= 1) { if (tid < s) red[tid] += red[tid + s]; __syncthreads(); }
    float inv = 1.f / red[0];
    __syncthreads();
    for (int o = tid; o < OUTD; o += 256)
        out[(size_t)n * OUTD + o] = expf(lg[o] - mx) * inv;
}

// ---------------- host orchestration ----------------
extern "C" void kernel_launch(void* const* d_in, const int* in_sizes, int n_in,
                              void* d_out, int out_size)
{
    const float* images   = (const float*)d_in[0];
    const float* W_map    = (const float*)d_in[1];
    const float* b_map    = (const float*)d_in[2];
    const float* cls      = (const float*)d_in[3];
    const float* pos      = (const float*)d_in[4];
    const float* ln1_g    = (const float*)d_in[5];
    const float* ln1_b    = (const float*)d_in[6];
    const float* Wq       = (const float*)d_in[7];
    const float* bq       = (const float*)d_in[8];
    const float* Wk       = (const float*)d_in[9];
    const float* bk       = (const float*)d_in[10];
    const float* Wv       = (const float*)d_in[11];
    const float* bv       = (const float*)d_in[12];
    const float* ln2_g    = (const float*)d_in[13];
    const float* ln2_b    = (const float*)d_in[14];
    const float* W1       = (const float*)d_in[15];
    const float* b1       = (const float*)d_in[16];
    const float* W2       = (const float*)d_in[17];
    const float* b2       = (const float*)d_in[18];
    const float* W_head   = (const float*)d_in[19];
    const float* b_head   = (const float*)d_in[20];
    float* out = (float*)d_out;

    __half *p_patches16, *p_h16, *p_mlp16, *p_q16, *p_k16, *p_vT16;
    __half *p_wmapT16, *p_w1T16, *p_w2T16, *p_wqT16, *p_wkT16, *p_wvT16;
    float *p_tokens, *p_x;
    cudaGetSymbolAddress((void**)&p_patches16, g_patches16);
    cudaGetSymbolAddress((void**)&p_tokens, g_tokens);
    cudaGetSymbolAddress((void**)&p_x, g_x);
    cudaGetSymbolAddress((void**)&p_h16, g_h16);
    cudaGetSymbolAddress((void**)&p_q16, g_q16);
    cudaGetSymbolAddress((void**)&p_k16, g_k16);
    cudaGetSymbolAddress((void**)&p_vT16, g_vT16);
    cudaGetSymbolAddress((void**)&p_mlp16, g_mlp16);
    cudaGetSymbolAddress((void**)&p_wmapT16, g_wmapT16);
    cudaGetSymbolAddress((void**)&p_w1T16, g_w1T16);
    cudaGetSymbolAddress((void**)&p_w2T16, g_w2T16);
    cudaGetSymbolAddress((void**)&p_wqT16, g_wqT16);
    cudaGetSymbolAddress((void**)&p_wkT16, g_wkT16);
    cudaGetSymbolAddress((void**)&p_wvT16, g_wvT16);

    cudaFuncSetAttribute(tgemm16<0>, cudaFuncAttributeMaxDynamicSharedMemorySize, TG16_SMEM);
    cudaFuncSetAttribute(tgemm16<1>, cudaFuncAttributeMaxDynamicSharedMemorySize, TG16_SMEM);
    cudaFuncSetAttribute(tgemm16<2>, cudaFuncAttributeMaxDynamicSharedMemorySize, TG16_SMEM);

    // 0) weight prep (fp16, transposed, K-interleaved)
    {
        dim3 gmap(DMODEL / 32, IN_DIM / 32, 1);
        cvtT16_kernel<<<gmap, 256>>>(W_map, p_wmapT16, IN_DIM, DMODEL);
        dim3 g1(MLPD / 32, DMODEL / 32, LAYERS);
        cvtT16_kernel<<<g1, 256>>>(W1, p_w1T16, DMODEL, MLPD);
        dim3 g2(DMODEL / 32, MLPD / 32, LAYERS);
        cvtT16_kernel<<<g2, 256>>>(W2, p_w2T16, MLPD, DMODEL);
        dim3 gq(2, 2, LAYERS * NHEAD);
        cvtT16_kernel<<<gq, 256>>>(Wq, p_wqT16, DHEAD, DHEAD);
        cvtT16_kernel<<<gq, 256>>>(Wk, p_wkT16, DHEAD, DHEAD);
        cvtT16_kernel<<<gq, 256>>>(Wv, p_wvT16, DHEAD, DHEAD);
    }

    // 1) patchify + embed + assemble
    patchify_kernel<<<(NP * IN_DIM) / 256, 256>>>(images);
    {
        dim3 grid(DMODEL / 128, NP / 128);   // 6 x 49
        tgemm16<0><<<grid, 128, TG16_SMEM>>>(p_patches16, p_wmapT16, b_map, nullptr,
                                             p_tokens, NP, DMODEL, IN_DIM);
    }
    assemble_kernel<<<(NS * DMODEL) / 256, 256>>>(p_tokens, cls, pos);

    // 2) transformer blocks
    for (int l = 0; l < LAYERS; l++) {
        ln_h_kernel<<<NS, 256>>>(p_x, ln1_g + l * DMODEL, ln1_b + l * DMODEL, p_h16);

        {
            dim3 grid((NS + 63) / 64, NHEAD, 3);
            qkv16_kernel<<<grid, 128>>>(p_h16,
                p_wqT16 + (size_t)l * NHEAD * DHEAD * DHEAD,
                p_wkT16 + (size_t)l * NHEAD * DHEAD * DHEAD,
                p_wvT16 + (size_t)l * NHEAD * DHEAD * DHEAD,
                bq + (size_t)l * NHEAD * DHEAD,
                bk + (size_t)l * NHEAD * DHEAD,
                bv + (size_t)l * NHEAD * DHEAD,
                p_q16, p_k16, p_vT16);
        }
        {
            dim3 grid((SEQ + 63) / 64, NB * NHEAD);
            attn16_kernel<<<grid, 128>>>(p_q16, p_k16, p_vT16, p_x);
        }

        ln_h_kernel<<<NS, 256>>>(p_x, ln2_g + l * DMODEL, ln2_b + l * DMODEL, p_h16);
        {
            dim3 grid(MLPD / 128, (NS + 127) / 128);   // 24 x 50
            tgemm16<1><<<grid, 128, TG16_SMEM>>>(p_h16, p_w1T16 + (size_t)l * DMODEL * MLPD,
                                                 b1 + (size_t)l * MLPD, nullptr,
                                                 p_mlp16, NS, MLPD, DMODEL);
        }
        {
            dim3 grid(DMODEL / 128, (NS + 127) / 128); // 6 x 50
            tgemm16<2><<<grid, 128, TG16_SMEM>>>(p_mlp16, p_w2T16 + (size_t)l * MLPD * DMODEL,
                                                 b2 + (size_t)l * DMODEL, p_x,
                                                 p_x, NS, DMODEL, MLPD);
        }
    }

    // 3) head + softmax
    head_kernel<<<NB, 256>>>(p_x, W_head, b_head, out);
}